// round 15
// baseline (speedup 1.0000x reference)
#include <cuda_runtime.h>
#include <math.h>

typedef unsigned long long ull;

#define E_ 128
#define N_ 384

// ---------------- device scratch ----------------
__device__ float g_qkout[E_ * 768];   // q | k | v
__device__ float g_x[E_ * 256];       // after norm2
__device__ float g_pe[N_ * 384];
__device__ float g_offatt[N_ * 384];  // off(256) | attw logits(128)
__device__ float g_ref[N_ * 2];
__device__ int   g_lx[N_ * 4];
__device__ int   g_ly[N_ * 4];
__device__ float g_agg[N_ * 2048];    // raw aggregated src rows per (n,h)
__device__ float g_csum[N_ * 8];
__device__ float g_Wc[384 * 640];     // combined [offw;attww]@l0w
__device__ float g_biasc[384];

// ---------------- helpers ----------------
__device__ __forceinline__ ull pack2(float lo, float hi) {
    ull r;
    asm("mov.b64 %0, {%1, %2};" : "=l"(r)
        : "r"(__float_as_uint(lo)), "r"(__float_as_uint(hi)));
    return r;
}
__device__ __forceinline__ void fma2(ull& d, ull a, ull b) {
    asm("fma.rn.f32x2 %0, %1, %2, %0;" : "+l"(d) : "l"(a), "l"(b));
}
__device__ __forceinline__ float2 unpack2(ull v) {
    unsigned lo, hi;
    asm("mov.b64 {%0, %1}, %2;" : "=r"(lo), "=r"(hi) : "l"(v));
    return make_float2(__uint_as_float(lo), __uint_as_float(hi));
}
__device__ __forceinline__ float dot4(float4 a, float4 b) {
    return a.x * b.x + a.y * b.y + a.z * b.z + a.w * b.w;
}
__device__ __forceinline__ float warp_sum(float v) {
#pragma unroll
    for (int o = 16; o; o >>= 1) v += __shfl_xor_sync(0xffffffffu, v, o);
    return v;
}
__device__ __forceinline__ float warp_max(float v) {
#pragma unroll
    for (int o = 16; o; o >>= 1) v = fmaxf(v, __shfl_xor_sync(0xffffffffu, v, o));
    return v;
}
__device__ __forceinline__ float block_ln256(float y, const float* w, const float* b, int t) {
    __shared__ float red[8];
    int lane = t & 31, wp = t >> 5;
    float s = warp_sum(y);
    if (lane == 0) red[wp] = s;
    __syncthreads();
    float tot = 0.f;
#pragma unroll
    for (int i = 0; i < 8; i++) tot += red[i];
    float mean = tot * (1.0f / 256.0f);
    __syncthreads();
    float dev = y - mean;
    float s2 = warp_sum(dev * dev);
    if (lane == 0) red[wp] = s2;
    __syncthreads();
    float tot2 = 0.f;
#pragma unroll
    for (int i = 0; i < 8; i++) tot2 += red[i];
    float var = tot2 * (1.0f / 256.0f);
    return dev * rsqrtf(var + 1e-5f) * w[t] + b[t];
}
// layernorm over 256 elems held by one half (8 warps) of a 512-thread block
__device__ __forceinline__ float ln_half(float y, float gw, float gb,
                                         int lane, int wp8, float* red) {
    float s = warp_sum(y);
    if (lane == 0) red[wp8] = s;
    __syncthreads();
    float tot = 0.f;
#pragma unroll
    for (int i = 0; i < 8; i++) tot += red[i];
    float mean = tot * (1.0f / 256.0f);
    __syncthreads();
    float dev = y - mean;
    float s2 = warp_sum(dev * dev);
    if (lane == 0) red[wp8] = s2;
    __syncthreads();
    float tot2 = 0.f;
#pragma unroll
    for (int i = 0; i < 8; i++) tot2 += red[i];
    return dev * rsqrtf(tot2 * (1.0f / 256.0f) + 1e-5f) * gw + gb;
}

// ================= shared GEMM core (used only for Wc, overlapped) ==========
__device__ __forceinline__ void gemm_core(
    const float* __restrict__ A, const float* __restrict__ A2,
    const float* __restrict__ W, const float* __restrict__ bias,
    float* __restrict__ C, int O, int K,
    int a2lim, int amode, int wmode, int wstride,
    int m0, int o0, float* sm)
{
    int t = threadIdx.x;
    float* As = sm;
    float* Ws = sm + 1088;
    int tx = t & 15, mi = t >> 4;
    int ar = mi, ac = tx * 2;
    int wr = t & 63, wcb = (t >> 6) * 8;

    bool addA2 = (amode == 1) && (o0 < a2lim);
    const float* Wrow = W + (size_t)(o0 + wr) * K;

    ull acc01a = pack2(0.f, 0.f), acc23a = pack2(0.f, 0.f);
    ull acc01b = pack2(0.f, 0.f), acc23b = pack2(0.f, 0.f);
    int nk = K >> 5;
    float2 pa;
    float pwv[8];

    auto fetch = [&](int kt) {
        int kgA = kt * 32 + ac;
        int m = m0 + ar;
        if (amode == 3) {
            const float* row = (m < 256) ? (A + (size_t)m * K)
                                         : (A2 + (size_t)(m - 256) * K);
            pa = *(const float2*)(row + kgA);
        } else {
            float2 x = *(const float2*)(A + (size_t)m * K + kgA);
            if (addA2) {
                float2 q = *(const float2*)(A2 + (size_t)m * K + kgA);
                x.x += q.x; x.y += q.y;
            }
            pa = x;
        }
        if (wmode == 0) {
            float4 w0 = *(const float4*)(Wrow + kt * 32 + wcb);
            float4 w1 = *(const float4*)(Wrow + kt * 32 + wcb + 4);
            pwv[0] = w0.x; pwv[1] = w0.y; pwv[2] = w0.z; pwv[3] = w0.w;
            pwv[4] = w1.x; pwv[5] = w1.y; pwv[6] = w1.z; pwv[7] = w1.w;
        } else {
#pragma unroll
            for (int i = 0; i < 8; i++)
                pwv[i] = W[(size_t)(kt * 32 + wcb + i) * wstride + o0 + wr];
        }
    };
    auto store = [&](int s) {
        float* as = As + s * 544;
        float* ws = Ws + s * 2304;
        *(float2*)(as + ar * 34 + ac) = pa;
#pragma unroll
        for (int i = 0; i < 8; i++) ws[(wcb + i) * 72 + wr] = pwv[i];
    };

    fetch(0);
    store(0);
    __syncthreads();
    for (int kt = 0; kt < nk; kt++) {
        int s = kt & 1;
        if (kt + 1 < nk) fetch(kt + 1);
        const float* as = As + s * 544;
        const float* ws = Ws + s * 2304;
#pragma unroll
        for (int kk = 0; kk < 16; kk++) {
            {
                float a = as[mi * 34 + kk];
                ull ap = pack2(a, a);
                float4 w4 = *(const float4*)(ws + kk * 72 + tx * 4);
                fma2(acc01a, ap, pack2(w4.x, w4.y));
                fma2(acc23a, ap, pack2(w4.z, w4.w));
            }
            {
                float a = as[mi * 34 + kk + 16];
                ull ap = pack2(a, a);
                float4 w4 = *(const float4*)(ws + (kk + 16) * 72 + tx * 4);
                fma2(acc01b, ap, pack2(w4.x, w4.y));
                fma2(acc23b, ap, pack2(w4.z, w4.w));
            }
        }
        if (kt + 1 < nk) {
            __syncthreads();
            store(s ^ 1);
            __syncthreads();
        }
    }

    float2 p0a = unpack2(acc01a), p1a = unpack2(acc23a);
    float2 p0b = unpack2(acc01b), p1b = unpack2(acc23b);
    float vals[4] = {p0a.x + p0b.x, p0a.y + p0b.y, p1a.x + p1b.x, p1a.y + p1b.y};
    int m = m0 + mi;
    float4 outv;
    float* ov = (float*)&outv;
#pragma unroll
    for (int j = 0; j < 4; j++) {
        int o = o0 + tx * 4 + j;
        ov[j] = vals[j] + (bias ? bias[o] : 0.f);
    }
    *(float4*)(C + (size_t)m * O + o0 + tx * 4) = outv;
}

// ================= geometry + PE =================
__device__ void geom_pe(const float* __restrict__ edge, int n, int k, float T) {
    int e = n / 3, p = n % 3;
    float ax = edge[e * 4 + 0], ay = edge[e * 4 + 1];
    float bx = edge[e * 4 + 2], by = edge[e * 4 + 3];
    float tpar = (float)p / 2.0f;
    float ptx = ax + tpar * (bx - ax);
    float pty = ay + tpar * (by - ay);
    float cxf = floorf(ptx), cyf = floorf(pty);
    int icx = (int)cxf, icy = (int)cyf;
    int minx = max(icx - 128, 0); if (minx + 256 > 2048) minx = 1792;
    int miny = max(icy - 128, 0); if (miny + 256 > 2048) miny = 1792;
    float fminx = (float)minx, fminy = (float)miny;
    float dx = bx - ax, dy = by - ay;

    float tlx, thx, tly, thy;
    {
        float safe = (dx == 0.f) ? 1.f : dx;
        float t1 = (fminx - ax) / safe, t2 = (fminx + 256.f - ax) / safe;
        tlx = (dx == 0.f) ? 0.f : fminf(t1, t2);
        thx = (dx == 0.f) ? 1.f : fmaxf(t1, t2);
    }
    {
        float safe = (dy == 0.f) ? 1.f : dy;
        float t1 = (fminy - ay) / safe, t2 = (fminy + 256.f - ay) / safe;
        tly = (dy == 0.f) ? 0.f : fminf(t1, t2);
        thy = (dy == 0.f) ? 1.f : fmaxf(t1, t2);
    }
    float t0 = fmaxf(fmaxf(tlx, tly), 0.f);
    float t1v = fmaxf(fminf(fminf(thx, thy), 1.f), t0);
    float cax = ax + t0 * dx, cay = ay + t0 * dy;
    float cbx = ax + t1v * dx, cby = ay + t1v * dy;

    float posx[3] = {cax, cbx, (float)icx};
    float posy[3] = {cay, cby, (float)icy};
    float* pe = g_pe + (size_t)n * 384;
    float invT = 1.0f / T;
#pragma unroll
    for (int comp = 0; comp < 3; comp++) {
        float sy, cy2, sx, cx2;
        sincosf(posy[comp] * invT, &sy, &cy2);
        sincosf(posx[comp] * invT, &sx, &cx2);
        pe[comp * 128 + 2 * k]          = sy;
        pe[comp * 128 + 2 * k + 1]      = cy2;
        pe[comp * 128 + 64 + 2 * k]     = sx;
        pe[comp * 128 + 64 + 2 * k + 1] = cx2;
    }
    if (k == 0) {
        g_ref[n * 2 + 0] = ((float)icx - fminx) / 256.f;
        g_ref[n * 2 + 1] = ((float)icy - fminy) / 256.f;
        const float ratio[4] = {8.f, 16.f, 32.f, 64.f};
#pragma unroll
        for (int l = 0; l < 4; l++) {
            g_lx[n * 4 + l] = (int)rintf(fminx / ratio[l]);
            g_ly[n * 4 + l] = (int)rintf(fminy / ratio[l]);
        }
    }
}

// ================= k_qkv: barrier-free warp-matvec =================
// 96 blocks x 256 thr. Warp owns output column o = blk*8 + warp; W row in regs.
__global__ __launch_bounds__(256) void k_qkv(
    const float* __restrict__ tgt, const float* __restrict__ qpos,
    const float* __restrict__ inw, const float* __restrict__ inb)
{
    int t = threadIdx.x;
    int w = t >> 5, lane = t & 31;
    int o = blockIdx.x * 8 + w;
    bool addq = (o < 512);
    const float4* wr = (const float4*)(inw + (size_t)o * 256);
    float4 w0 = __ldg(wr + lane), w1 = __ldg(wr + 32 + lane);
    float b = __ldg(inb + o);
    for (int m = 0; m < 128; m += 2) {
        const float4* a0p = (const float4*)(tgt + (size_t)m * 256);
        const float4* a1p = (const float4*)(tgt + (size_t)(m + 1) * 256);
        float4 a00 = a0p[lane], a01 = a0p[32 + lane];
        float4 a10 = a1p[lane], a11 = a1p[32 + lane];
        if (addq) {
            const float4* q0p = (const float4*)(qpos + (size_t)m * 256);
            const float4* q1p = (const float4*)(qpos + (size_t)(m + 1) * 256);
            float4 q00 = q0p[lane], q01 = q0p[32 + lane];
            float4 q10 = q1p[lane], q11 = q1p[32 + lane];
            a00.x += q00.x; a00.y += q00.y; a00.z += q00.z; a00.w += q00.w;
            a01.x += q01.x; a01.y += q01.y; a01.z += q01.z; a01.w += q01.w;
            a10.x += q10.x; a10.y += q10.y; a10.z += q10.z; a10.w += q10.w;
            a11.x += q11.x; a11.y += q11.y; a11.z += q11.z; a11.w += q11.w;
        }
        float p0 = dot4(w0, a00) + dot4(w1, a01);
        float p1 = dot4(w0, a10) + dot4(w1, a11);
        p0 = warp_sum(p0); p1 = warp_sum(p1);
        if (lane == 0) g_qkout[(size_t)m * 768 + o] = p0 + b;
        if (lane == 1) g_qkout[(size_t)(m + 1) * 768 + o] = p1 + b;
    }
}

// ================= phase2: attn (blocks 0-127) + Wc + geomPE + biasc =========
__global__ __launch_bounds__(256) void k_phase2(
    const float* __restrict__ wo, const float* __restrict__ bo,
    const float* __restrict__ tgt,
    const float* __restrict__ n2w, const float* __restrict__ n2b,
    const float* __restrict__ edge,
    const float* __restrict__ offw, const float* __restrict__ attww,
    const float* __restrict__ offb, const float* __restrict__ attwb,
    const float* __restrict__ l0w, const float* __restrict__ l0b)
{
    __shared__ float sm[5696];
    int bx = blockIdx.x;
    int t = threadIdx.x;

    if (bx >= 128) {
        if (bx < 368) {
            int idx = bx - 128;
            gemm_core(offw, attww, l0w, nullptr, g_Wc, 640, 256,
                      0, 3, 1, 640, (idx / 10) * 16, (idx % 10) * 64, sm);
        } else if (bx < 416) {
            float* Ts = sm;
            if (t < 32) Ts[t] = (float)pow(10000.0, (double)t / 32.0);
            __syncthreads();
            int g = bx - 368;
            geom_pe(edge, g * 8 + (t >> 5), t & 31, Ts[t & 31]);
        } else {
            int gw = (bx - 416) * 8 + (t >> 5), lane = t & 31;
            float4 b0 = *(const float4*)(l0b + lane * 4);
            float4 b1 = *(const float4*)(l0b + 128 + lane * 4);
            for (int i = 0; i < 24; i++) {
                int r = gw * 24 + i;
                const float* row = (r < 256) ? (offw + (size_t)r * 256)
                                             : (attww + (size_t)(r - 256) * 256);
                float4 w0 = *(const float4*)(row + lane * 4);
                float4 w1 = *(const float4*)(row + 128 + lane * 4);
                float p = dot4(w0, b0) + dot4(w1, b1);
                p = warp_sum(p);
                if (lane == 0)
                    g_biasc[r] = p + (r < 256 ? offb[r] : attwb[r - 256]);
            }
        }
        return;
    }

    // ---- attention for edge e = bx ----
    int e = bx;
    float* sq = sm;           // 256
    float* sc = sm + 256;     // 1024
    float* so = sm + 1280;    // 256
    float* sy = sm + 1536;    // 256
    int wp = t >> 5, lane = t & 31;

    sq[t] = g_qkout[e * 768 + t];
    __syncthreads();

    {
        int hq = lane >> 2, qd = lane & 3;
        float4 q0 = *(const float4*)(sq + hq * 32 + qd * 8);
        float4 q1 = *(const float4*)(sq + hq * 32 + qd * 8 + 4);
        const float scale = 0.17677669529663687f;
#pragma unroll 4
        for (int i = 0; i < 16; i++) {
            int f = wp + i * 8;
            const float4* kr = (const float4*)(g_qkout + (size_t)f * 768 + 256);
            float4 k0 = __ldg(kr + lane * 2);
            float4 k1 = __ldg(kr + lane * 2 + 1);
            float p = dot4(q0, k0) + dot4(q1, k1);
            p += __shfl_xor_sync(0xffffffffu, p, 1);
            p += __shfl_xor_sync(0xffffffffu, p, 2);
            if ((lane & 3) == 0) sc[hq * 128 + f] = p * scale;
        }
    }
    __syncthreads();
    {
        float vals[4];
        float m = -1e30f;
#pragma unroll
        for (int i = 0; i < 4; i++) { vals[i] = sc[wp * 128 + lane + 32 * i]; m = fmaxf(m, vals[i]); }
        m = warp_max(m);
        float sum = 0.f;
#pragma unroll
        for (int i = 0; i < 4; i++) { vals[i] = expf(vals[i] - m); sum += vals[i]; }
        sum = warp_sum(sum);
        float inv = 1.0f / sum;
#pragma unroll
        for (int i = 0; i < 4; i++) sc[wp * 128 + lane + 32 * i] = vals[i] * inv;
    }
    __syncthreads();
    {
        int h = t >> 5;
        float acc = 0.f;
#pragma unroll 4
        for (int f = 0; f < 128; f++)
            acc += sc[h * 128 + f] * __ldg(g_qkout + (size_t)f * 768 + 512 + t);
        so[t] = acc;
    }
    __syncthreads();
    {
        const float4* so4 = (const float4*)so;
        float4 s0 = so4[lane], s1 = so4[32 + lane];
#pragma unroll 4
        for (int i = 0; i < 32; i++) {
            int o = wp * 32 + i;
            const float4* r = (const float4*)(wo + (size_t)o * 256);
            float p = dot4(__ldg(r + lane), s0) + dot4(__ldg(r + 32 + lane), s1);
            p = warp_sum(p);
            if (lane == 0) sy[o] = p;
        }
    }
    __syncthreads();
    float y = tgt[e * 256 + t] + sy[t] + bo[t];
    g_x[e * 256 + t] = block_ln256(y, n2w, n2b, t);
}

// ================= k_offatt: barrier-free warp-matvec =================
// 48 blocks x 256 thr. Warp owns output row o = blk*8 + warp of g_offatt.
// Wc row (640 floats) lives in 5 float4/lane. Loop over 128 edges x 3 points.
__global__ __launch_bounds__(256) void k_offatt(const float* __restrict__ qpos)
{
    int t = threadIdx.x;
    int w = t >> 5, lane = t & 31;
    int o = blockIdx.x * 8 + w;
    const float4* wr = (const float4*)(g_Wc + (size_t)o * 640);
    float4 wv[5];
#pragma unroll
    for (int j = 0; j < 5; j++) wv[j] = __ldg(wr + j * 32 + lane);
    float b = g_biasc[o];

    for (int e = 0; e < 128; e++) {
        const float4* xp = (const float4*)(g_x + (size_t)e * 256);
        const float4* qp = (const float4*)(qpos + (size_t)e * 256);
        float4 x0 = xp[lane], x1 = xp[32 + lane];
        float4 q0 = __ldg(qp + lane), q1 = __ldg(qp + 32 + lane);
        x0.x += q0.x; x0.y += q0.y; x0.z += q0.z; x0.w += q0.w;
        x1.x += q1.x; x1.y += q1.y; x1.z += q1.z; x1.w += q1.w;
        float base = dot4(wv[0], x0) + dot4(wv[1], x1);
#pragma unroll
        for (int p = 0; p < 3; p++) {
            int n = e * 3 + p;
            const float4* pep = (const float4*)(g_pe + (size_t)n * 384);
            float4 e0 = pep[lane], e1 = pep[32 + lane], e2 = pep[64 + lane];
            float s = base + dot4(wv[2], e0) + dot4(wv[3], e1) + dot4(wv[4], e2);
            s = warp_sum(s);
            if (lane == 0) g_offatt[(size_t)n * 384 + o] = s + b;
        }
    }
}

// ================= sample: tap precompute + gather (raw agg out) =============
__global__ __launch_bounds__(512) void k_sample2(
    const float* __restrict__ src, const unsigned char* __restrict__ msk,
    const float* __restrict__ vr)
{
    int n = blockIdx.x, t = threadIdx.x;
    __shared__ float sloc[256];
    __shared__ float saw[128];
    __shared__ float mh[8], sh[8];
    __shared__ __align__(8) float2 std_[512];    // {pix (bitcast), coeff}
    if (t >= 256 && t < 384) saw[t - 256] = g_offatt[n * 384 + t];
    if (t < 256) {
        const float slen[4] = {32.f, 16.f, 8.f, 4.f};
        int l = (t >> 3) & 3, xy = t & 1;
        float off = g_offatt[n * 384 + t];
        sloc[t] = g_ref[n * 2 + xy] * vr[l * 2 + xy] + off / slen[l];
    }
    __syncthreads();
    if (t < 8) {
        float m = -1e30f;
        for (int i = 0; i < 16; i++) m = fmaxf(m, saw[t * 16 + i]);
        float s = 0.f;
        for (int i = 0; i < 16; i++) s += expf(saw[t * 16 + i] - m);
        mh[t] = m; sh[t] = s;
    }
    __syncthreads();
    if (t < 128) {
        int h = t >> 4;
        saw[t] = expf(saw[t] - mh[h]) / sh[h];
    }
    __syncthreads();

    {
        int h = t >> 6, l = (t >> 4) & 3, p = (t >> 2) & 3, tp = t & 3;
        const int s_arr[4]  = {32, 16, 8, 4};
        const int w_arr[4]  = {256, 128, 64, 32};
        const int st_arr[4] = {0, 65536, 81920, 86016};
        int s = s_arr[l], W = w_arr[l], base = st_arr[l];
        int lxl = g_lx[n * 4 + l], lyl = g_ly[n * 4 + l];
        float gx = sloc[h * 32 + l * 8 + p * 2 + 0];
        float gy = sloc[h * 32 + l * 8 + p * 2 + 1];
        float a  = saw[h * 16 + l * 4 + p];
        float px = gx * (float)s - 0.5f;
        float py = gy * (float)s - 0.5f;
        float fx0 = floorf(px), fy0 = floorf(py);
        int x0 = (int)fx0, y0 = (int)fy0;
        float fx = px - fx0, fy = py - fy0;
        int xi = x0 + (tp & 1), yi = y0 + (tp >> 1);
        float wx = (tp & 1) ? fx : (1.f - fx);
        float wy = (tp >> 1) ? fy : (1.f - fy);
        bool ok = (xi >= 0) & (xi < s) & (yi >= 0) & (yi < s);
        int xc = min(max(xi, 0), s - 1);
        int yc = min(max(yi, 0), s - 1);
        int pix = base + (lyl + yc) * W + (lxl + xc);
        ok = ok && !msk[pix];
        float c = ok ? a * (wx * wy) : 0.f;
        std_[t] = make_float2(__int_as_float(pix), c);
    }
    __syncthreads();

    int w = t >> 5;
    int h = w >> 1, half = w & 1, lane = t & 31;
    int doff = half * 32 + lane;
    ulonglong2 acc;
    acc.x = pack2(0.f, 0.f);
    acc.y = pack2(0.f, 0.f);
    float csum = 0.f;
    const float2* taps = std_ + h * 64;
#pragma unroll 8
    for (int i = 0; i < 64; i++) {
        float2 e2 = taps[i];
        int pix = __float_as_int(e2.x);
        float c = e2.y;
        csum += c;
        ull cp = pack2(c, c);
        ulonglong2 v = __ldg((const ulonglong2*)(src + (size_t)pix * 256) + doff);
        fma2(acc.x, cp, v.x);
        fma2(acc.y, cp, v.y);
    }
    ((ulonglong2*)(g_agg + (size_t)n * 2048 + h * 256))[doff] = acc;
    if (half == 0 && lane == 0) g_csum[n * 8 + h] = csum;
}

// ================= tail: pooled valproj + oproj + LN1 + FFN + LN3 ===========
__global__ __launch_bounds__(512) void k_tail(
    const float* __restrict__ valw, const float* __restrict__ valb,
    const float* __restrict__ oprojw, const float* __restrict__ oprojb,
    const float* __restrict__ n1w, const float* __restrict__ n1b,
    const float* __restrict__ l1w, const float* __restrict__ l1b,
    const float* __restrict__ l2w, const float* __restrict__ l2b,
    const float* __restrict__ n3w, const float* __restrict__ n3b,
    float* __restrict__ out)
{
    __shared__ __align__(16) float sop[512];
    __shared__ float sy[512];
    __shared__ __align__(16) float sx2[512];
    __shared__ __align__(16) float shid[2048];
    __shared__ float sf[512];
    __shared__ float red[16];

    int t = threadIdx.x;
    int w = t >> 5, lane = t & 31;
    int ei = t >> 8, tt = t & 255, wp8 = tt >> 5;
    int e0 = blockIdx.x * 2;
    int e = e0 + ei;

    // ---- value projection on pooled agg ----
    {
        int h = w >> 1;
        int jb = (w & 1) * 16;
        const float4* a0p = (const float4*)(g_agg + (size_t)(3 * e0 + 0) * 2048 + h * 256);
        const float4* a1p = (const float4*)(g_agg + (size_t)(3 * e0 + 1) * 2048 + h * 256);
        const float4* a2p = (const float4*)(g_agg + (size_t)(3 * e0 + 2) * 2048 + h * 256);
        const float4* b0p = (const float4*)(g_agg + (size_t)(3 * e0 + 3) * 2048 + h * 256);
        const float4* b1p = (const float4*)(g_agg + (size_t)(3 * e0 + 4) * 2048 + h * 256);
        const float4* b2p = (const float4*)(g_agg + (size_t)(3 * e0 + 5) * 2048 + h * 256);
        const float third = 1.f / 3.f;
        float4 u, v, z;
        u = a0p[lane]; v = a1p[lane]; z = a2p[lane];
        float4 av0 = make_float4((u.x + v.x + z.x) * third, (u.y + v.y + z.y) * third,
                                 (u.z + v.z + z.z) * third, (u.w + v.w + z.w) * third);
        u = a0p[32 + lane]; v = a1p[32 + lane]; z = a2p[32 + lane];
        float4 av1 = make_float4((u.x + v.x + z.x) * third, (u.y + v.y + z.y) * third,
                                 (u.z + v.z + z.z) * third, (u.w + v.w + z.w) * third);
        u = b0p[lane]; v = b1p[lane]; z = b2p[lane];
        float4 bv0 = make_float4((u.x + v.x + z.x) * third, (u.y + v.y + z.y) * third,
                                 (u.z + v.z + z.z) * third, (u.w + v.w + z.w) * third);
        u = b0p[32 + lane]; v = b1p[32 + lane]; z = b2p[32 + lane];
        float4 bv1 = make_float4((u.x + v.x + z.x) * third, (u.y + v.y + z.y) * third,
                                 (u.z + v.z + z.z) * third, (u.w + v.w + z.w) * third);
        float csa = (g_csum[(3 * e0 + 0) * 8 + h] + g_csum[(3 * e0 + 1) * 8 + h] +
                     g_csum[(3 * e0 + 2) * 8 + h]) * third;
        float csb = (g_csum[(3 * e0 + 3) * 8 + h] + g_csum[(3 * e0 + 4) * 8 + h] +
                     g_csum[(3 * e0 + 5) * 8 + h]) * third;
#pragma unroll 4
        for (int i = 0; i < 16; i++) {
            int o = h * 32 + jb + i;
            const float4* r = (const float4*)(valw + (size_t)o * 256);
            float4 w0 = __ldg(r + lane), w1 = __ldg(r + 32 + lane);
            float pa = dot4(w0, av0) + dot4(w1, av1);
            float pb = dot4(w0, bv0) + dot4(w1, bv1);
            pa = warp_sum(pa); pb = warp_sum(pb);
            float vb = __ldg(valb + o);
            if (lane == 0) sop[o] = pa + csa * vb;
            if (lane == 1) sop[256 + o] = pb + csb * vb;
        }
    }
    __syncthreads();

    // ---- oproj for both edges ----
    {
        const float4* m0 = (const float4*)sop;
        const float4* m1 = (const float4*)(sop + 256);
        float4 a0 = m0[lane], a1 = m0[32 + lane];
        float4 b0 = m1[lane], b1 = m1[32 + lane];
#pragma unroll
        for (int i = 0; i < 16; i += 2) {
            int o = w * 16 + i;
            const float4* r0 = (const float4*)(oprojw + (size_t)o * 256);
            const float4* r1 = (const float4*)(oprojw + (size_t)(o + 1) * 256);
            float4 w00 = __ldg(r0 + lane), w01 = __ldg(r0 + 32 + lane);
            float4 w10 = __ldg(r1 + lane), w11 = __ldg(r1 + 32 + lane);
            float p00 = dot4(w00, a0) + dot4(w01, a1);
            float p01 = dot4(w10, a0) + dot4(w11, a1);
            float p10 = dot4(w00, b0) + dot4(w01, b1);
            float p11 = dot4(w10, b0) + dot4(w11, b1);
            p00 = warp_sum(p00); p01 = warp_sum(p01);
            p10 = warp_sum(p10); p11 = warp_sum(p11);
            if (lane == 0) sy[o] = p00;
            if (lane == 1) sy[o + 1] = p01;
            if (lane == 2) sy[256 + o] = p10;
            if (lane == 3) sy[256 + o + 1] = p11;
        }
    }
    __syncthreads();
    // ---- residual + norm1 ----
    {
        float y = g_x[(size_t)e * 256 + tt] + sy[ei * 256 + tt] + oprojb[tt];
        float x2 = ln_half(y, n1w[tt], n1b[tt], lane, wp8, red + ei * 8);
        sx2[ei * 256 + tt] = x2;
    }
    __syncthreads();

    // ---- FFN1 + relu ----
    {
        const float4* x0p = (const float4*)sx2;
        const float4* x1p = (const float4*)(sx2 + 256);
        float4 x00 = x0p[lane], x01 = x0p[32 + lane];
        float4 x10 = x1p[lane], x11 = x1p[32 + lane];
        for (int i = 0; i < 64; i += 2) {
            int o = w * 64 + i;
            const float4* r0 = (const float4*)(l1w + (size_t)o * 256);
            const float4* r1 = (const float4*)(l1w + (size_t)(o + 1) * 256);
            float4 w00 = __ldg(r0 + lane), w01 = __ldg(r0 + 32 + lane);
            float4 w10 = __ldg(r1 + lane), w11 = __ldg(r1 + 32 + lane);
            float p00 = dot4(w00, x00) + dot4(w01, x01);
            float p01 = dot4(w10, x00) + dot4(w11, x01);
            float p10 = dot4(w00, x10) + dot4(w01, x11);
            float p11 = dot4(w10, x10) + dot4(w11, x11);
            p00 = warp_sum(p00); p01 = warp_sum(p01);
            p10 = warp_sum(p10); p11 = warp_sum(p11);
            if (lane == 0) shid[o] = fmaxf(p00 + l1b[o], 0.f);
            if (lane == 1) shid[o + 1] = fmaxf(p01 + l1b[o + 1], 0.f);
            if (lane == 2) shid[1024 + o] = fmaxf(p10 + l1b[o], 0.f);
            if (lane == 3) shid[1024 + o + 1] = fmaxf(p11 + l1b[o + 1], 0.f);
        }
    }
    __syncthreads();
    // ---- FFN2 ----
    {
        const float4* h0p = (const float4*)shid;
        const float4* h1p = (const float4*)(shid + 1024);
#pragma unroll
        for (int i = 0; i < 16; i += 2) {
            int o = w * 16 + i;
            const float4* r0 = (const float4*)(l2w + (size_t)o * 1024);
            const float4* r1 = (const float4*)(l2w + (size_t)(o + 1) * 1024);
            float p00 = 0.f, p01 = 0.f, p10 = 0.f, p11 = 0.f;
#pragma unroll
            for (int j = 0; j < 8; j++) {
                float4 wv0 = __ldg(r0 + j * 32 + lane);
                float4 wv1 = __ldg(r1 + j * 32 + lane);
                float4 h0 = h0p[j * 32 + lane];
                float4 h1 = h1p[j * 32 + lane];
                p00 += dot4(wv0, h0); p01 += dot4(wv1, h0);
                p10 += dot4(wv0, h1); p11 += dot4(wv1, h1);
            }
            p00 = warp_sum(p00); p01 = warp_sum(p01);
            p10 = warp_sum(p10); p11 = warp_sum(p11);
            if (lane == 0) sf[o] = p00;
            if (lane == 1) sf[o + 1] = p01;
            if (lane == 2) sf[256 + o] = p10;
            if (lane == 3) sf[256 + o + 1] = p11;
        }
    }
    __syncthreads();
    // ---- residual + norm3 -> out ----
    {
        float y = sx2[ei * 256 + tt] + sf[ei * 256 + tt] + l2b[tt];
        out[(size_t)e * 256 + tt] = ln_half(y, n3w[tt], n3b[tt], lane, wp8, red + ei * 8);
    }
}

// ================= launch =================
extern "C" void kernel_launch(void* const* d_in, const int* in_sizes, int n_in,
                              void* d_out, int out_size) {
    const float* tgt      = (const float*)d_in[0];
    const float* qpos     = (const float*)d_in[1];
    const float* edge     = (const float*)d_in[2];
    const float* src      = (const float*)d_in[3];
    const unsigned char* msk = (const unsigned char*)d_in[4];
    const float* vr       = (const float*)d_in[5];
    const float* inw      = (const float*)d_in[6];
    const float* inb      = (const float*)d_in[7];
    const float* ow       = (const float*)d_in[8];
    const float* ob       = (const float*)d_in[9];
    const float* n1w      = (const float*)d_in[10];
    const float* n1b      = (const float*)d_in[11];
    const float* n2w      = (const float*)d_in[12];
    const float* n2b      = (const float*)d_in[13];
    const float* n3w      = (const float*)d_in[14];
    const float* n3b      = (const float*)d_in[15];
    const float* l0w      = (const float*)d_in[16];
    const float* l0b      = (const float*)d_in[17];
    const float* l1w      = (const float*)d_in[18];
    const float* l1b      = (const float*)d_in[19];
    const float* l2w      = (const float*)d_in[20];
    const float* l2b      = (const float*)d_in[21];
    const float* offw     = (const float*)d_in[22];
    const float* offb     = (const float*)d_in[23];
    const float* attww    = (const float*)d_in[24];
    const float* attwb    = (const float*)d_in[25];
    const float* valw     = (const float*)d_in[26];
    const float* valb     = (const float*)d_in[27];
    const float* oprojw   = (const float*)d_in[28];
    const float* oprojb   = (const float*)d_in[29];
    float* out = (float*)d_out;

    // 1. QKV (barrier-free warp-matvec)
    k_qkv<<<96, 256>>>(tgt, qpos, inw, inb);
    // 2. attn first (blocks 0-127) + overlapped Wc GEMM / geometry / bias
    k_phase2<<<418, 256>>>(ow, ob, tgt, n2w, n2b, edge,
                           offw, attww, offb, attwb, l0w, l0b);
    // 3. offsets + attention logits (barrier-free warp-matvec)
    k_offatt<<<48, 256>>>(qpos);
    // 4. deformable sampling (L2-bound floor ~15 us)
    k_sample2<<<384, 512>>>(src, msk, vr);
    // 5. pooled valproj + oproj + LN1 + FFN + LN3 (2 edges/block, 64 blocks)
    k_tail<<<64, 512>>>(valw, valb, oprojw, oprojb, n1w, n1b,
                        l1w, l1b, l2w, l2b, n3w, n3b, out);
}

// round 16
// speedup vs baseline: 2.4508x; 2.4508x over previous
#include <cuda_runtime.h>
#include <math.h>

typedef unsigned long long ull;

#define E_ 128
#define N_ 384

// ---------------- device scratch ----------------
__device__ float g_qkout[E_ * 768];   // q | k | v
__device__ float g_x[E_ * 256];       // after norm2
__device__ float g_pe[N_ * 384];
__device__ float g_offatt[N_ * 384];  // off(256) | attw logits(128)
__device__ float g_ref[N_ * 2];
__device__ int   g_lx[N_ * 4];
__device__ int   g_ly[N_ * 4];
__device__ float g_agg[N_ * 2048];    // raw aggregated src rows per (n,h)
__device__ float g_csum[N_ * 8];
__device__ float g_Wc[384 * 640];     // combined [offw;attww]@l0w
__device__ float g_biasc[384];

// ---------------- helpers ----------------
__device__ __forceinline__ ull pack2(float lo, float hi) {
    ull r;
    asm("mov.b64 %0, {%1, %2};" : "=l"(r)
        : "r"(__float_as_uint(lo)), "r"(__float_as_uint(hi)));
    return r;
}
__device__ __forceinline__ void fma2(ull& d, ull a, ull b) {
    asm("fma.rn.f32x2 %0, %1, %2, %0;" : "+l"(d) : "l"(a), "l"(b));
}
__device__ __forceinline__ float2 unpack2(ull v) {
    unsigned lo, hi;
    asm("mov.b64 {%0, %1}, %2;" : "=r"(lo), "=r"(hi) : "l"(v));
    return make_float2(__uint_as_float(lo), __uint_as_float(hi));
}
__device__ __forceinline__ float dot4(float4 a, float4 b) {
    return a.x * b.x + a.y * b.y + a.z * b.z + a.w * b.w;
}
__device__ __forceinline__ float warp_sum(float v) {
#pragma unroll
    for (int o = 16; o; o >>= 1) v += __shfl_xor_sync(0xffffffffu, v, o);
    return v;
}
__device__ __forceinline__ float warp_max(float v) {
#pragma unroll
    for (int o = 16; o; o >>= 1) v = fmaxf(v, __shfl_xor_sync(0xffffffffu, v, o));
    return v;
}
__device__ __forceinline__ float block_ln256(float y, const float* w, const float* b, int t) {
    __shared__ float red[8];
    int lane = t & 31, wp = t >> 5;
    float s = warp_sum(y);
    if (lane == 0) red[wp] = s;
    __syncthreads();
    float tot = 0.f;
#pragma unroll
    for (int i = 0; i < 8; i++) tot += red[i];
    float mean = tot * (1.0f / 256.0f);
    __syncthreads();
    float dev = y - mean;
    float s2 = warp_sum(dev * dev);
    if (lane == 0) red[wp] = s2;
    __syncthreads();
    float tot2 = 0.f;
#pragma unroll
    for (int i = 0; i < 8; i++) tot2 += red[i];
    float var = tot2 * (1.0f / 256.0f);
    return dev * rsqrtf(var + 1e-5f) * w[t] + b[t];
}
// layernorm over 256 elems held by one half (8 warps) of a 512-thread block
__device__ __forceinline__ float ln_half(float y, float gw, float gb,
                                         int lane, int wp8, float* red) {
    float s = warp_sum(y);
    if (lane == 0) red[wp8] = s;
    __syncthreads();
    float tot = 0.f;
#pragma unroll
    for (int i = 0; i < 8; i++) tot += red[i];
    float mean = tot * (1.0f / 256.0f);
    __syncthreads();
    float dev = y - mean;
    float s2 = warp_sum(dev * dev);
    if (lane == 0) red[wp8] = s2;
    __syncthreads();
    float tot2 = 0.f;
#pragma unroll
    for (int i = 0; i < 8; i++) tot2 += red[i];
    return dev * rsqrtf(tot2 * (1.0f / 256.0f) + 1e-5f) * gw + gb;
}

// ================= shared GEMM core: 16(M) x 64(O), f32x2, 4 acc chains ======
__device__ __forceinline__ void gemm_core(
    const float* __restrict__ A, const float* __restrict__ A2,
    const float* __restrict__ W, const float* __restrict__ bias,
    float* __restrict__ C, int O, int K,
    int a2lim, int amode, int wmode, int wstride,
    int m0, int o0, float* sm)
{
    int t = threadIdx.x;
    float* As = sm;          // 2 * 16 * 34 = 1088
    float* Ws = sm + 1088;   // 2 * 32 * 72 = 4608
    int tx = t & 15, mi = t >> 4;
    int ar = mi, ac = tx * 2;
    int wr = t & 63, wcb = (t >> 6) * 8;

    bool addA2 = (amode == 1) && (o0 < a2lim);
    const float* Wrow = W + (size_t)(o0 + wr) * K;

    ull acc01a = pack2(0.f, 0.f), acc23a = pack2(0.f, 0.f);
    ull acc01b = pack2(0.f, 0.f), acc23b = pack2(0.f, 0.f);
    int nk = K >> 5;
    float2 pa;
    float pwv[8];

    auto fetch = [&](int kt) {
        int kgA = kt * 32 + ac;
        int m = m0 + ar;
        if (amode == 2) {
            if (kgA < 256) {
                int e = m / 3;
                float2 x = *(const float2*)(A + (size_t)e * 256 + kgA);
                float2 q = *(const float2*)(A2 + (size_t)e * 256 + kgA);
                pa = make_float2(x.x + q.x, x.y + q.y);
            } else {
                pa = *(const float2*)(g_pe + (size_t)m * 384 + (kgA - 256));
            }
        } else if (amode == 3) {
            const float* row = (m < 256) ? (A + (size_t)m * K)
                                         : (A2 + (size_t)(m - 256) * K);
            pa = *(const float2*)(row + kgA);
        } else {
            float2 x = *(const float2*)(A + (size_t)m * K + kgA);
            if (addA2) {
                float2 q = *(const float2*)(A2 + (size_t)m * K + kgA);
                x.x += q.x; x.y += q.y;
            }
            pa = x;
        }
        if (wmode == 0) {
            float4 w0 = *(const float4*)(Wrow + kt * 32 + wcb);
            float4 w1 = *(const float4*)(Wrow + kt * 32 + wcb + 4);
            pwv[0] = w0.x; pwv[1] = w0.y; pwv[2] = w0.z; pwv[3] = w0.w;
            pwv[4] = w1.x; pwv[5] = w1.y; pwv[6] = w1.z; pwv[7] = w1.w;
        } else {
#pragma unroll
            for (int i = 0; i < 8; i++)
                pwv[i] = W[(size_t)(kt * 32 + wcb + i) * wstride + o0 + wr];
        }
    };
    auto store = [&](int s) {
        float* as = As + s * 544;
        float* ws = Ws + s * 2304;
        *(float2*)(as + ar * 34 + ac) = pa;
#pragma unroll
        for (int i = 0; i < 8; i++) ws[(wcb + i) * 72 + wr] = pwv[i];
    };

    fetch(0);
    store(0);
    __syncthreads();
    for (int kt = 0; kt < nk; kt++) {
        int s = kt & 1;
        if (kt + 1 < nk) fetch(kt + 1);
        const float* as = As + s * 544;
        const float* ws = Ws + s * 2304;
#pragma unroll
        for (int kk = 0; kk < 16; kk++) {
            {
                float a = as[mi * 34 + kk];
                ull ap = pack2(a, a);
                float4 w4 = *(const float4*)(ws + kk * 72 + tx * 4);
                fma2(acc01a, ap, pack2(w4.x, w4.y));
                fma2(acc23a, ap, pack2(w4.z, w4.w));
            }
            {
                float a = as[mi * 34 + kk + 16];
                ull ap = pack2(a, a);
                float4 w4 = *(const float4*)(ws + (kk + 16) * 72 + tx * 4);
                fma2(acc01b, ap, pack2(w4.x, w4.y));
                fma2(acc23b, ap, pack2(w4.z, w4.w));
            }
        }
        if (kt + 1 < nk) {
            __syncthreads();
            store(s ^ 1);
            __syncthreads();
        }
    }

    float2 p0a = unpack2(acc01a), p1a = unpack2(acc23a);
    float2 p0b = unpack2(acc01b), p1b = unpack2(acc23b);
    float vals[4] = {p0a.x + p0b.x, p0a.y + p0b.y, p1a.x + p1b.x, p1a.y + p1b.y};
    int m = m0 + mi;
    float4 outv;
    float* ov = (float*)&outv;
#pragma unroll
    for (int j = 0; j < 4; j++) {
        int o = o0 + tx * 4 + j;
        ov[j] = vals[j] + (bias ? bias[o] : 0.f);
    }
    *(float4*)(C + (size_t)m * O + o0 + tx * 4) = outv;
}

// ================= geometry + PE: one thread = one (point n, frequency k) ====
__device__ void geom_pe(const float* __restrict__ edge, int n, int k, float T) {
    int e = n / 3, p = n % 3;
    float ax = edge[e * 4 + 0], ay = edge[e * 4 + 1];
    float bx = edge[e * 4 + 2], by = edge[e * 4 + 3];
    float tpar = (float)p / 2.0f;
    float ptx = ax + tpar * (bx - ax);
    float pty = ay + tpar * (by - ay);
    float cxf = floorf(ptx), cyf = floorf(pty);
    int icx = (int)cxf, icy = (int)cyf;
    int minx = max(icx - 128, 0); if (minx + 256 > 2048) minx = 1792;
    int miny = max(icy - 128, 0); if (miny + 256 > 2048) miny = 1792;
    float fminx = (float)minx, fminy = (float)miny;
    float dx = bx - ax, dy = by - ay;

    float tlx, thx, tly, thy;
    {
        float safe = (dx == 0.f) ? 1.f : dx;
        float t1 = (fminx - ax) / safe, t2 = (fminx + 256.f - ax) / safe;
        tlx = (dx == 0.f) ? 0.f : fminf(t1, t2);
        thx = (dx == 0.f) ? 1.f : fmaxf(t1, t2);
    }
    {
        float safe = (dy == 0.f) ? 1.f : dy;
        float t1 = (fminy - ay) / safe, t2 = (fminy + 256.f - ay) / safe;
        tly = (dy == 0.f) ? 0.f : fminf(t1, t2);
        thy = (dy == 0.f) ? 1.f : fmaxf(t1, t2);
    }
    float t0 = fmaxf(fmaxf(tlx, tly), 0.f);
    float t1v = fmaxf(fminf(fminf(thx, thy), 1.f), t0);
    float cax = ax + t0 * dx, cay = ay + t0 * dy;
    float cbx = ax + t1v * dx, cby = ay + t1v * dy;

    float posx[3] = {cax, cbx, (float)icx};
    float posy[3] = {cay, cby, (float)icy};
    float* pe = g_pe + (size_t)n * 384;
    float invT = 1.0f / T;
#pragma unroll
    for (int comp = 0; comp < 3; comp++) {
        float sy, cy2, sx, cx2;
        sincosf(posy[comp] * invT, &sy, &cy2);
        sincosf(posx[comp] * invT, &sx, &cx2);
        pe[comp * 128 + 2 * k]          = sy;
        pe[comp * 128 + 2 * k + 1]      = cy2;
        pe[comp * 128 + 64 + 2 * k]     = sx;
        pe[comp * 128 + 64 + 2 * k + 1] = cx2;
    }
    if (k == 0) {
        g_ref[n * 2 + 0] = ((float)icx - fminx) / 256.f;
        g_ref[n * 2 + 1] = ((float)icy - fminy) / 256.f;
        const float ratio[4] = {8.f, 16.f, 32.f, 64.f};
#pragma unroll
        for (int l = 0; l < 4; l++) {
            g_lx[n * 4 + l] = (int)rintf(fminx / ratio[l]);
            g_ly[n * 4 + l] = (int)rintf(fminy / ratio[l]);
        }
    }
}

// ================= k_qkv: QKV projection only =================
__global__ __launch_bounds__(256) void k_qkv(
    const float* __restrict__ tgt, const float* __restrict__ qpos,
    const float* __restrict__ inw, const float* __restrict__ inb)
{
    __shared__ float sm[5696];
    gemm_core(tgt, qpos, inw, inb, g_qkout, 768, 256,
              512, 1, 0, 0, blockIdx.y * 16, blockIdx.x * 64, sm);
}

// ================= phase2: attn (blocks 0-127) + Wc + geomPE + biasc =========
__global__ __launch_bounds__(256) void k_phase2(
    const float* __restrict__ wo, const float* __restrict__ bo,
    const float* __restrict__ tgt,
    const float* __restrict__ n2w, const float* __restrict__ n2b,
    const float* __restrict__ edge,
    const float* __restrict__ offw, const float* __restrict__ attww,
    const float* __restrict__ offb, const float* __restrict__ attwb,
    const float* __restrict__ l0w, const float* __restrict__ l0b)
{
    __shared__ float sm[5696];
    int bx = blockIdx.x;
    int t = threadIdx.x;

    if (bx >= 128) {
        if (bx < 368) {
            int idx = bx - 128;
            gemm_core(offw, attww, l0w, nullptr, g_Wc, 640, 256,
                      0, 3, 1, 640, (idx / 10) * 16, (idx % 10) * 64, sm);
        } else if (bx < 416) {
            float* Ts = sm;
            if (t < 32) Ts[t] = (float)pow(10000.0, (double)t / 32.0);
            __syncthreads();
            int g = bx - 368;
            geom_pe(edge, g * 8 + (t >> 5), t & 31, Ts[t & 31]);
        } else {
            int gw = (bx - 416) * 8 + (t >> 5), lane = t & 31;
            float4 b0 = *(const float4*)(l0b + lane * 4);
            float4 b1 = *(const float4*)(l0b + 128 + lane * 4);
            for (int i = 0; i < 24; i++) {
                int r = gw * 24 + i;
                const float* row = (r < 256) ? (offw + (size_t)r * 256)
                                             : (attww + (size_t)(r - 256) * 256);
                float4 w0 = *(const float4*)(row + lane * 4);
                float4 w1 = *(const float4*)(row + 128 + lane * 4);
                float p = dot4(w0, b0) + dot4(w1, b1);
                p = warp_sum(p);
                if (lane == 0)
                    g_biasc[r] = p + (r < 256 ? offb[r] : attwb[r - 256]);
            }
        }
        return;
    }

    // ---- attention for edge e = bx ----
    int e = bx;
    float* sq = sm;           // 256
    float* sc = sm + 256;     // 1024
    float* so = sm + 1280;    // 256
    float* sy = sm + 1536;    // 256
    int wp = t >> 5, lane = t & 31;

    sq[t] = g_qkout[e * 768 + t];
    __syncthreads();

    {
        int hq = lane >> 2, qd = lane & 3;
        float4 q0 = *(const float4*)(sq + hq * 32 + qd * 8);
        float4 q1 = *(const float4*)(sq + hq * 32 + qd * 8 + 4);
        const float scale = 0.17677669529663687f;
#pragma unroll 4
        for (int i = 0; i < 16; i++) {
            int f = wp + i * 8;
            const float4* kr = (const float4*)(g_qkout + (size_t)f * 768 + 256);
            float4 k0 = __ldg(kr + lane * 2);
            float4 k1 = __ldg(kr + lane * 2 + 1);
            float p = dot4(q0, k0) + dot4(q1, k1);
            p += __shfl_xor_sync(0xffffffffu, p, 1);
            p += __shfl_xor_sync(0xffffffffu, p, 2);
            if ((lane & 3) == 0) sc[hq * 128 + f] = p * scale;
        }
    }
    __syncthreads();
    {
        float vals[4];
        float m = -1e30f;
#pragma unroll
        for (int i = 0; i < 4; i++) { vals[i] = sc[wp * 128 + lane + 32 * i]; m = fmaxf(m, vals[i]); }
        m = warp_max(m);
        float sum = 0.f;
#pragma unroll
        for (int i = 0; i < 4; i++) { vals[i] = expf(vals[i] - m); sum += vals[i]; }
        sum = warp_sum(sum);
        float inv = 1.0f / sum;
#pragma unroll
        for (int i = 0; i < 4; i++) sc[wp * 128 + lane + 32 * i] = vals[i] * inv;
    }
    __syncthreads();
    {
        int h = t >> 5;
        float acc = 0.f;
#pragma unroll 4
        for (int f = 0; f < 128; f++)
            acc += sc[h * 128 + f] * __ldg(g_qkout + (size_t)f * 768 + 512 + t);
        so[t] = acc;
    }
    __syncthreads();
    {
        const float4* so4 = (const float4*)so;
        float4 s0 = so4[lane], s1 = so4[32 + lane];
#pragma unroll 4
        for (int i = 0; i < 32; i++) {
            int o = wp * 32 + i;
            const float4* r = (const float4*)(wo + (size_t)o * 256);
            float p = dot4(__ldg(r + lane), s0) + dot4(__ldg(r + 32 + lane), s1);
            p = warp_sum(p);
            if (lane == 0) sy[o] = p;
        }
    }
    __syncthreads();
    float y = tgt[e * 256 + t] + sy[t] + bo[t];
    g_x[e * 256 + t] = block_ln256(y, n2w, n2b, t);
}

// ================= offatt = Wc @ [x+qpos | pe] + bias' =================
__global__ __launch_bounds__(256) void k_offatt(const float* __restrict__ qpos)
{
    __shared__ float sm[5696];
    gemm_core(g_x, qpos, g_Wc, g_biasc, g_offatt, 384, 640,
              0, 2, 0, 0, blockIdx.y * 16, blockIdx.x * 64, sm);
}

// ================= sample: tap precompute + gather (raw agg out) =============
__global__ __launch_bounds__(512) void k_sample2(
    const float* __restrict__ src, const unsigned char* __restrict__ msk,
    const float* __restrict__ vr)
{
    int n = blockIdx.x, t = threadIdx.x;
    __shared__ float sloc[256];
    __shared__ float saw[128];
    __shared__ float mh[8], sh[8];
    __shared__ __align__(8) float2 std_[512];    // {pix (bitcast), coeff}
    if (t >= 256 && t < 384) saw[t - 256] = g_offatt[n * 384 + t];
    if (t < 256) {
        const float slen[4] = {32.f, 16.f, 8.f, 4.f};
        int l = (t >> 3) & 3, xy = t & 1;
        float off = g_offatt[n * 384 + t];
        sloc[t] = g_ref[n * 2 + xy] * vr[l * 2 + xy] + off / slen[l];
    }
    __syncthreads();
    if (t < 8) {
        float m = -1e30f;
        for (int i = 0; i < 16; i++) m = fmaxf(m, saw[t * 16 + i]);
        float s = 0.f;
        for (int i = 0; i < 16; i++) s += expf(saw[t * 16 + i] - m);
        mh[t] = m; sh[t] = s;
    }
    __syncthreads();
    if (t < 128) {
        int h = t >> 4;
        saw[t] = expf(saw[t] - mh[h]) / sh[h];
    }
    __syncthreads();

    {
        int h = t >> 6, l = (t >> 4) & 3, p = (t >> 2) & 3, tp = t & 3;
        const int s_arr[4]  = {32, 16, 8, 4};
        const int w_arr[4]  = {256, 128, 64, 32};
        const int st_arr[4] = {0, 65536, 81920, 86016};
        int s = s_arr[l], W = w_arr[l], base = st_arr[l];
        int lxl = g_lx[n * 4 + l], lyl = g_ly[n * 4 + l];
        float gx = sloc[h * 32 + l * 8 + p * 2 + 0];
        float gy = sloc[h * 32 + l * 8 + p * 2 + 1];
        float a  = saw[h * 16 + l * 4 + p];
        float px = gx * (float)s - 0.5f;
        float py = gy * (float)s - 0.5f;
        float fx0 = floorf(px), fy0 = floorf(py);
        int x0 = (int)fx0, y0 = (int)fy0;
        float fx = px - fx0, fy = py - fy0;
        int xi = x0 + (tp & 1), yi = y0 + (tp >> 1);
        float wx = (tp & 1) ? fx : (1.f - fx);
        float wy = (tp >> 1) ? fy : (1.f - fy);
        bool ok = (xi >= 0) & (xi < s) & (yi >= 0) & (yi < s);
        int xc = min(max(xi, 0), s - 1);
        int yc = min(max(yi, 0), s - 1);
        int pix = base + (lyl + yc) * W + (lxl + xc);
        ok = ok && !msk[pix];
        float c = ok ? a * (wx * wy) : 0.f;
        std_[t] = make_float2(__int_as_float(pix), c);
    }
    __syncthreads();

    int w = t >> 5;
    int h = w >> 1, half = w & 1, lane = t & 31;
    int doff = half * 32 + lane;
    ulonglong2 acc;
    acc.x = pack2(0.f, 0.f);
    acc.y = pack2(0.f, 0.f);
    float csum = 0.f;
    const float2* taps = std_ + h * 64;
#pragma unroll 8
    for (int i = 0; i < 64; i++) {
        float2 e2 = taps[i];
        int pix = __float_as_int(e2.x);
        float c = e2.y;
        csum += c;
        ull cp = pack2(c, c);
        ulonglong2 v = __ldg((const ulonglong2*)(src + (size_t)pix * 256) + doff);
        fma2(acc.x, cp, v.x);
        fma2(acc.y, cp, v.y);
    }
    ((ulonglong2*)(g_agg + (size_t)n * 2048 + h * 256))[doff] = acc;
    if (half == 0 && lane == 0) g_csum[n * 8 + h] = csum;
}

// ================= tail: pooled valproj + oproj + LN1 + FFN + LN3 ===========
// 64 blocks, 512 threads, 2 edges/block (R10-proven structure).
__global__ __launch_bounds__(512) void k_tail(
    const float* __restrict__ valw, const float* __restrict__ valb,
    const float* __restrict__ oprojw, const float* __restrict__ oprojb,
    const float* __restrict__ n1w, const float* __restrict__ n1b,
    const float* __restrict__ l1w, const float* __restrict__ l1b,
    const float* __restrict__ l2w, const float* __restrict__ l2b,
    const float* __restrict__ n3w, const float* __restrict__ n3b,
    float* __restrict__ out)
{
    __shared__ __align__(16) float sop[512];
    __shared__ float sy[512];
    __shared__ __align__(16) float sx2[512];
    __shared__ __align__(16) float shid[2048];
    __shared__ float sf[512];
    __shared__ float red[16];

    int t = threadIdx.x;
    int w = t >> 5, lane = t & 31;
    int ei = t >> 8, tt = t & 255, wp8 = tt >> 5;
    int e0 = blockIdx.x * 2;
    int e = e0 + ei;

    // ---- value projection on pooled agg (weights shared across both edges) --
    {
        int h = w >> 1;
        int jb = (w & 1) * 16;
        const float4* a0p = (const float4*)(g_agg + (size_t)(3 * e0 + 0) * 2048 + h * 256);
        const float4* a1p = (const float4*)(g_agg + (size_t)(3 * e0 + 1) * 2048 + h * 256);
        const float4* a2p = (const float4*)(g_agg + (size_t)(3 * e0 + 2) * 2048 + h * 256);
        const float4* b0p = (const float4*)(g_agg + (size_t)(3 * e0 + 3) * 2048 + h * 256);
        const float4* b1p = (const float4*)(g_agg + (size_t)(3 * e0 + 4) * 2048 + h * 256);
        const float4* b2p = (const float4*)(g_agg + (size_t)(3 * e0 + 5) * 2048 + h * 256);
        const float third = 1.f / 3.f;
        float4 u, v, z;
        u = a0p[lane]; v = a1p[lane]; z = a2p[lane];
        float4 av0 = make_float4((u.x + v.x + z.x) * third, (u.y + v.y + z.y) * third,
                                 (u.z + v.z + z.z) * third, (u.w + v.w + z.w) * third);
        u = a0p[32 + lane]; v = a1p[32 + lane]; z = a2p[32 + lane];
        float4 av1 = make_float4((u.x + v.x + z.x) * third, (u.y + v.y + z.y) * third,
                                 (u.z + v.z + z.z) * third, (u.w + v.w + z.w) * third);
        u = b0p[lane]; v = b1p[lane]; z = b2p[lane];
        float4 bv0 = make_float4((u.x + v.x + z.x) * third, (u.y + v.y + z.y) * third,
                                 (u.z + v.z + z.z) * third, (u.w + v.w + z.w) * third);
        u = b0p[32 + lane]; v = b1p[32 + lane]; z = b2p[32 + lane];
        float4 bv1 = make_float4((u.x + v.x + z.x) * third, (u.y + v.y + z.y) * third,
                                 (u.z + v.z + z.z) * third, (u.w + v.w + z.w) * third);
        float csa = (g_csum[(3 * e0 + 0) * 8 + h] + g_csum[(3 * e0 + 1) * 8 + h] +
                     g_csum[(3 * e0 + 2) * 8 + h]) * third;
        float csb = (g_csum[(3 * e0 + 3) * 8 + h] + g_csum[(3 * e0 + 4) * 8 + h] +
                     g_csum[(3 * e0 + 5) * 8 + h]) * third;
#pragma unroll 4
        for (int i = 0; i < 16; i++) {
            int o = h * 32 + jb + i;
            const float4* r = (const float4*)(valw + (size_t)o * 256);
            float4 w0 = __ldg(r + lane), w1 = __ldg(r + 32 + lane);
            float pa = dot4(w0, av0) + dot4(w1, av1);
            float pb = dot4(w0, bv0) + dot4(w1, bv1);
            pa = warp_sum(pa); pb = warp_sum(pb);
            float vb = __ldg(valb + o);
            if (lane == 0) sop[o] = pa + csa * vb;
            if (lane == 1) sop[256 + o] = pb + csb * vb;
        }
    }
    __syncthreads();

    // ---- oproj for both edges, weights loaded once ----
    {
        const float4* m0 = (const float4*)sop;
        const float4* m1 = (const float4*)(sop + 256);
        float4 a0 = m0[lane], a1 = m0[32 + lane];
        float4 b0 = m1[lane], b1 = m1[32 + lane];
#pragma unroll
        for (int i = 0; i < 16; i += 2) {
            int o = w * 16 + i;
            const float4* r0 = (const float4*)(oprojw + (size_t)o * 256);
            const float4* r1 = (const float4*)(oprojw + (size_t)(o + 1) * 256);
            float4 w00 = __ldg(r0 + lane), w01 = __ldg(r0 + 32 + lane);
            float4 w10 = __ldg(r1 + lane), w11 = __ldg(r1 + 32 + lane);
            float p00 = dot4(w00, a0) + dot4(w01, a1);
            float p01 = dot4(w10, a0) + dot4(w11, a1);
            float p10 = dot4(w00, b0) + dot4(w01, b1);
            float p11 = dot4(w10, b0) + dot4(w11, b1);
            p00 = warp_sum(p00); p01 = warp_sum(p01);
            p10 = warp_sum(p10); p11 = warp_sum(p11);
            if (lane == 0) sy[o] = p00;
            if (lane == 1) sy[o + 1] = p01;
            if (lane == 2) sy[256 + o] = p10;
            if (lane == 3) sy[256 + o + 1] = p11;
        }
    }
    __syncthreads();
    // ---- residual + norm1 ----
    {
        float y = g_x[(size_t)e * 256 + tt] + sy[ei * 256 + tt] + oprojb[tt];
        float x2 = ln_half(y, n1w[tt], n1b[tt], lane, wp8, red + ei * 8);
        sx2[ei * 256 + tt] = x2;
    }
    __syncthreads();

    // ---- FFN1 + relu (1024 hidden, both edges) ----
    {
        const float4* x0p = (const float4*)sx2;
        const float4* x1p = (const float4*)(sx2 + 256);
        float4 x00 = x0p[lane], x01 = x0p[32 + lane];
        float4 x10 = x1p[lane], x11 = x1p[32 + lane];
        for (int i = 0; i < 64; i += 2) {
            int o = w * 64 + i;
            const float4* r0 = (const float4*)(l1w + (size_t)o * 256);
            const float4* r1 = (const float4*)(l1w + (size_t)(o + 1) * 256);
            float4 w00 = __ldg(r0 + lane), w01 = __ldg(r0 + 32 + lane);
            float4 w10 = __ldg(r1 + lane), w11 = __ldg(r1 + 32 + lane);
            float p00 = dot4(w00, x00) + dot4(w01, x01);
            float p01 = dot4(w10, x00) + dot4(w11, x01);
            float p10 = dot4(w00, x10) + dot4(w01, x11);
            float p11 = dot4(w10, x10) + dot4(w11, x11);
            p00 = warp_sum(p00); p01 = warp_sum(p01);
            p10 = warp_sum(p10); p11 = warp_sum(p11);
            if (lane == 0) shid[o] = fmaxf(p00 + l1b[o], 0.f);
            if (lane == 1) shid[o + 1] = fmaxf(p01 + l1b[o + 1], 0.f);
            if (lane == 2) shid[1024 + o] = fmaxf(p10 + l1b[o], 0.f);
            if (lane == 3) shid[1024 + o + 1] = fmaxf(p11 + l1b[o + 1], 0.f);
        }
    }
    __syncthreads();
    // ---- FFN2 (K=1024, both edges) ----
    {
        const float4* h0p = (const float4*)shid;
        const float4* h1p = (const float4*)(shid + 1024);
#pragma unroll
        for (int i = 0; i < 16; i += 2) {
            int o = w * 16 + i;
            const float4* r0 = (const float4*)(l2w + (size_t)o * 1024);
            const float4* r1 = (const float4*)(l2w + (size_t)(o + 1) * 1024);
            float p00 = 0.f, p01 = 0.f, p10 = 0.f, p11 = 0.f;
#pragma unroll
            for (int j = 0; j < 8; j++) {
                float4 wv0 = __ldg(r0 + j * 32 + lane);
                float4 wv1 = __ldg(r1 + j * 32 + lane);
                float4 h0 = h0p[j * 32 + lane];
                float4 h1 = h1p[j * 32 + lane];
                p00 += dot4(wv0, h0); p01 += dot4(wv1, h0);
                p10 += dot4(wv0, h1); p11 += dot4(wv1, h1);
            }
            p00 = warp_sum(p00); p01 = warp_sum(p01);
            p10 = warp_sum(p10); p11 = warp_sum(p11);
            if (lane == 0) sf[o] = p00;
            if (lane == 1) sf[o + 1] = p01;
            if (lane == 2) sf[256 + o] = p10;
            if (lane == 3) sf[256 + o + 1] = p11;
        }
    }
    __syncthreads();
    // ---- residual + norm3 -> out ----
    {
        float y = sx2[ei * 256 + tt] + sf[ei * 256 + tt] + l2b[tt];
        out[(size_t)e * 256 + tt] = ln_half(y, n3w[tt], n3b[tt], lane, wp8, red + ei * 8);
    }
}

// ================= launch =================
extern "C" void kernel_launch(void* const* d_in, const int* in_sizes, int n_in,
                              void* d_out, int out_size) {
    const float* tgt      = (const float*)d_in[0];
    const float* qpos     = (const float*)d_in[1];
    const float* edge     = (const float*)d_in[2];
    const float* src      = (const float*)d_in[3];
    const unsigned char* msk = (const unsigned char*)d_in[4];
    const float* vr       = (const float*)d_in[5];
    const float* inw      = (const float*)d_in[6];
    const float* inb      = (const float*)d_in[7];
    const float* ow       = (const float*)d_in[8];
    const float* ob       = (const float*)d_in[9];
    const float* n1w      = (const float*)d_in[10];
    const float* n1b      = (const float*)d_in[11];
    const float* n2w      = (const float*)d_in[12];
    const float* n2b      = (const float*)d_in[13];
    const float* n3w      = (const float*)d_in[14];
    const float* n3b      = (const float*)d_in[15];
    const float* l0w      = (const float*)d_in[16];
    const float* l0b      = (const float*)d_in[17];
    const float* l1w      = (const float*)d_in[18];
    const float* l1b      = (const float*)d_in[19];
    const float* l2w      = (const float*)d_in[20];
    const float* l2b      = (const float*)d_in[21];
    const float* offw     = (const float*)d_in[22];
    const float* offb     = (const float*)d_in[23];
    const float* attww    = (const float*)d_in[24];
    const float* attwb    = (const float*)d_in[25];
    const float* valw     = (const float*)d_in[26];
    const float* valb     = (const float*)d_in[27];
    const float* oprojw   = (const float*)d_in[28];
    const float* oprojb   = (const float*)d_in[29];
    float* out = (float*)d_out;

    // 1. QKV projection (small, fast — does NOT gate on Wc)
    k_qkv<<<dim3(12, 8), 256>>>(tgt, qpos, inw, inb);
    // 2. attn first (blocks 0-127) + overlapped Wc GEMM / geometry / bias
    k_phase2<<<418, 256>>>(ow, ob, tgt, n2w, n2b, edge,
                           offw, attww, offb, attwb, l0w, l0b);
    // 3. offsets + attention logits (single GEMM)
    k_offatt<<<dim3(6, 24), 256>>>(qpos);
    // 4. deformable sampling (L2-bound floor ~15 us)
    k_sample2<<<384, 512>>>(src, msk, vr);
    // 5. pooled valproj + oproj + LN1 + FFN + LN3 (2 edges/block, 64 blocks)
    k_tail<<<64, 512>>>(valw, valb, oprojw, oprojb, n1w, n1b,
                        l1w, l1b, l2w, l2b, n3w, n3b, out);
}

// round 17
// speedup vs baseline: 2.5454x; 1.0386x over previous
#include <cuda_runtime.h>
#include <math.h>

typedef unsigned long long ull;

#define E_ 128
#define N_ 384

// ---------------- device scratch ----------------
__device__ float g_qkout[E_ * 768];   // q | k | v
__device__ float g_x[E_ * 256];       // after norm2
__device__ float g_pe[N_ * 384];
__device__ float g_offatt[N_ * 384];  // split-K partial 0 (+bias)
__device__ float g_offatt2[N_ * 384]; // split-K partial 1
__device__ float g_ref[N_ * 2];
__device__ int   g_lx[N_ * 4];
__device__ int   g_ly[N_ * 4];
__device__ float g_agg[N_ * 2048];    // raw aggregated src rows per (n,h)
__device__ float g_csum[N_ * 8];
__device__ float g_Wc[384 * 640];     // combined [offw;attww]@l0w
__device__ float g_biasc[384];

// ---------------- helpers ----------------
__device__ __forceinline__ ull pack2(float lo, float hi) {
    ull r;
    asm("mov.b64 %0, {%1, %2};" : "=l"(r)
        : "r"(__float_as_uint(lo)), "r"(__float_as_uint(hi)));
    return r;
}
__device__ __forceinline__ void fma2(ull& d, ull a, ull b) {
    asm("fma.rn.f32x2 %0, %1, %2, %0;" : "+l"(d) : "l"(a), "l"(b));
}
__device__ __forceinline__ float2 unpack2(ull v) {
    unsigned lo, hi;
    asm("mov.b64 {%0, %1}, %2;" : "=r"(lo), "=r"(hi) : "l"(v));
    return make_float2(__uint_as_float(lo), __uint_as_float(hi));
}
__device__ __forceinline__ float dot4(float4 a, float4 b) {
    return a.x * b.x + a.y * b.y + a.z * b.z + a.w * b.w;
}
__device__ __forceinline__ float warp_sum(float v) {
#pragma unroll
    for (int o = 16; o; o >>= 1) v += __shfl_xor_sync(0xffffffffu, v, o);
    return v;
}
__device__ __forceinline__ float warp_max(float v) {
#pragma unroll
    for (int o = 16; o; o >>= 1) v = fmaxf(v, __shfl_xor_sync(0xffffffffu, v, o));
    return v;
}
__device__ __forceinline__ float block_ln256(float y, const float* w, const float* b, int t) {
    __shared__ float red[8];
    int lane = t & 31, wp = t >> 5;
    float s = warp_sum(y);
    if (lane == 0) red[wp] = s;
    __syncthreads();
    float tot = 0.f;
#pragma unroll
    for (int i = 0; i < 8; i++) tot += red[i];
    float mean = tot * (1.0f / 256.0f);
    __syncthreads();
    float dev = y - mean;
    float s2 = warp_sum(dev * dev);
    if (lane == 0) red[wp] = s2;
    __syncthreads();
    float tot2 = 0.f;
#pragma unroll
    for (int i = 0; i < 8; i++) tot2 += red[i];
    float var = tot2 * (1.0f / 256.0f);
    return dev * rsqrtf(var + 1e-5f) * w[t] + b[t];
}
// layernorm over 256 elems held by one half (8 warps) of a 512-thread block
__device__ __forceinline__ float ln_half(float y, float gw, float gb,
                                         int lane, int wp8, float* red) {
    float s = warp_sum(y);
    if (lane == 0) red[wp8] = s;
    __syncthreads();
    float tot = 0.f;
#pragma unroll
    for (int i = 0; i < 8; i++) tot += red[i];
    float mean = tot * (1.0f / 256.0f);
    __syncthreads();
    float dev = y - mean;
    float s2 = warp_sum(dev * dev);
    if (lane == 0) red[wp8] = s2;
    __syncthreads();
    float tot2 = 0.f;
#pragma unroll
    for (int i = 0; i < 8; i++) tot2 += red[i];
    return dev * rsqrtf(tot2 * (1.0f / 256.0f) + 1e-5f) * gw + gb;
}

// ================= shared GEMM core: 16(M) x 64(O), f32x2, 4 acc chains ======
// Computes C[m,o] = sum_{k in [kstart, kstart+kchunk)} A'[m,k]*W'[o,k] (+bias)
__device__ __forceinline__ void gemm_core(
    const float* __restrict__ A, const float* __restrict__ A2,
    const float* __restrict__ W, const float* __restrict__ bias,
    float* __restrict__ C, int O, int K,
    int a2lim, int amode, int wmode, int wstride,
    int m0, int o0, float* sm, int kstart, int kchunk)
{
    int t = threadIdx.x;
    float* As = sm;          // 2 * 16 * 34 = 1088
    float* Ws = sm + 1088;   // 2 * 32 * 72 = 4608
    int tx = t & 15, mi = t >> 4;
    int ar = mi, ac = tx * 2;
    int wr = t & 63, wcb = (t >> 6) * 8;

    bool addA2 = (amode == 1) && (o0 < a2lim);
    const float* Wrow = W + (size_t)(o0 + wr) * K;

    ull acc01a = pack2(0.f, 0.f), acc23a = pack2(0.f, 0.f);
    ull acc01b = pack2(0.f, 0.f), acc23b = pack2(0.f, 0.f);
    int nk = kchunk >> 5;
    float2 pa;
    float pwv[8];

    auto fetch = [&](int kt) {
        int kgA = kstart + kt * 32 + ac;
        int m = m0 + ar;
        if (amode == 2) {
            if (kgA < 256) {
                int e = m / 3;
                float2 x = *(const float2*)(A + (size_t)e * 256 + kgA);
                float2 q = *(const float2*)(A2 + (size_t)e * 256 + kgA);
                pa = make_float2(x.x + q.x, x.y + q.y);
            } else {
                pa = *(const float2*)(g_pe + (size_t)m * 384 + (kgA - 256));
            }
        } else if (amode == 3) {
            const float* row = (m < 256) ? (A + (size_t)m * K)
                                         : (A2 + (size_t)(m - 256) * K);
            pa = *(const float2*)(row + kgA);
        } else {
            float2 x = *(const float2*)(A + (size_t)m * K + kgA);
            if (addA2) {
                float2 q = *(const float2*)(A2 + (size_t)m * K + kgA);
                x.x += q.x; x.y += q.y;
            }
            pa = x;
        }
        int kgW = kstart + kt * 32 + wcb;
        if (wmode == 0) {
            float4 w0 = *(const float4*)(Wrow + kgW);
            float4 w1 = *(const float4*)(Wrow + kgW + 4);
            pwv[0] = w0.x; pwv[1] = w0.y; pwv[2] = w0.z; pwv[3] = w0.w;
            pwv[4] = w1.x; pwv[5] = w1.y; pwv[6] = w1.z; pwv[7] = w1.w;
        } else {
#pragma unroll
            for (int i = 0; i < 8; i++)
                pwv[i] = W[(size_t)(kgW + i) * wstride + o0 + wr];
        }
    };
    auto store = [&](int s) {
        float* as = As + s * 544;
        float* ws = Ws + s * 2304;
        *(float2*)(as + ar * 34 + ac) = pa;
#pragma unroll
        for (int i = 0; i < 8; i++) ws[(wcb + i) * 72 + wr] = pwv[i];
    };

    fetch(0);
    store(0);
    __syncthreads();
    for (int kt = 0; kt < nk; kt++) {
        int s = kt & 1;
        if (kt + 1 < nk) fetch(kt + 1);
        const float* as = As + s * 544;
        const float* ws = Ws + s * 2304;
#pragma unroll
        for (int kk = 0; kk < 16; kk++) {
            {
                float a = as[mi * 34 + kk];
                ull ap = pack2(a, a);
                float4 w4 = *(const float4*)(ws + kk * 72 + tx * 4);
                fma2(acc01a, ap, pack2(w4.x, w4.y));
                fma2(acc23a, ap, pack2(w4.z, w4.w));
            }
            {
                float a = as[mi * 34 + kk + 16];
                ull ap = pack2(a, a);
                float4 w4 = *(const float4*)(ws + (kk + 16) * 72 + tx * 4);
                fma2(acc01b, ap, pack2(w4.x, w4.y));
                fma2(acc23b, ap, pack2(w4.z, w4.w));
            }
        }
        if (kt + 1 < nk) {
            __syncthreads();
            store(s ^ 1);
            __syncthreads();
        }
    }

    float2 p0a = unpack2(acc01a), p1a = unpack2(acc23a);
    float2 p0b = unpack2(acc01b), p1b = unpack2(acc23b);
    float vals[4] = {p0a.x + p0b.x, p0a.y + p0b.y, p1a.x + p1b.x, p1a.y + p1b.y};
    int m = m0 + mi;
    float4 outv;
    float* ov = (float*)&outv;
#pragma unroll
    for (int j = 0; j < 4; j++) {
        int o = o0 + tx * 4 + j;
        ov[j] = vals[j] + (bias ? bias[o] : 0.f);
    }
    *(float4*)(C + (size_t)m * O + o0 + tx * 4) = outv;
}

// ================= geometry + PE: one thread = one (point n, frequency k) ====
__device__ void geom_pe(const float* __restrict__ edge, int n, int k, float T) {
    int e = n / 3, p = n % 3;
    float ax = edge[e * 4 + 0], ay = edge[e * 4 + 1];
    float bx = edge[e * 4 + 2], by = edge[e * 4 + 3];
    float tpar = (float)p / 2.0f;
    float ptx = ax + tpar * (bx - ax);
    float pty = ay + tpar * (by - ay);
    float cxf = floorf(ptx), cyf = floorf(pty);
    int icx = (int)cxf, icy = (int)cyf;
    int minx = max(icx - 128, 0); if (minx + 256 > 2048) minx = 1792;
    int miny = max(icy - 128, 0); if (miny + 256 > 2048) miny = 1792;
    float fminx = (float)minx, fminy = (float)miny;
    float dx = bx - ax, dy = by - ay;

    float tlx, thx, tly, thy;
    {
        float safe = (dx == 0.f) ? 1.f : dx;
        float t1 = (fminx - ax) / safe, t2 = (fminx + 256.f - ax) / safe;
        tlx = (dx == 0.f) ? 0.f : fminf(t1, t2);
        thx = (dx == 0.f) ? 1.f : fmaxf(t1, t2);
    }
    {
        float safe = (dy == 0.f) ? 1.f : dy;
        float t1 = (fminy - ay) / safe, t2 = (fminy + 256.f - ay) / safe;
        tly = (dy == 0.f) ? 0.f : fminf(t1, t2);
        thy = (dy == 0.f) ? 1.f : fmaxf(t1, t2);
    }
    float t0 = fmaxf(fmaxf(tlx, tly), 0.f);
    float t1v = fmaxf(fminf(fminf(thx, thy), 1.f), t0);
    float cax = ax + t0 * dx, cay = ay + t0 * dy;
    float cbx = ax + t1v * dx, cby = ay + t1v * dy;

    float posx[3] = {cax, cbx, (float)icx};
    float posy[3] = {cay, cby, (float)icy};
    float* pe = g_pe + (size_t)n * 384;
    float invT = 1.0f / T;
#pragma unroll
    for (int comp = 0; comp < 3; comp++) {
        float sy, cy2, sx, cx2;
        sincosf(posy[comp] * invT, &sy, &cy2);
        sincosf(posx[comp] * invT, &sx, &cx2);
        pe[comp * 128 + 2 * k]          = sy;
        pe[comp * 128 + 2 * k + 1]      = cy2;
        pe[comp * 128 + 64 + 2 * k]     = sx;
        pe[comp * 128 + 64 + 2 * k + 1] = cx2;
    }
    if (k == 0) {
        g_ref[n * 2 + 0] = ((float)icx - fminx) / 256.f;
        g_ref[n * 2 + 1] = ((float)icy - fminy) / 256.f;
        const float ratio[4] = {8.f, 16.f, 32.f, 64.f};
#pragma unroll
        for (int l = 0; l < 4; l++) {
            g_lx[n * 4 + l] = (int)rintf(fminx / ratio[l]);
            g_ly[n * 4 + l] = (int)rintf(fminy / ratio[l]);
        }
    }
}

// ================= k_qkv: QKV projection only =================
__global__ __launch_bounds__(256) void k_qkv(
    const float* __restrict__ tgt, const float* __restrict__ qpos,
    const float* __restrict__ inw, const float* __restrict__ inb)
{
    __shared__ float sm[5696];
    gemm_core(tgt, qpos, inw, inb, g_qkout, 768, 256,
              512, 1, 0, 0, blockIdx.y * 16, blockIdx.x * 64, sm, 0, 256);
}

// ================= phase2: attn (blocks 0-127) + Wc + geomPE + biasc =========
__global__ __launch_bounds__(256) void k_phase2(
    const float* __restrict__ wo, const float* __restrict__ bo,
    const float* __restrict__ tgt,
    const float* __restrict__ n2w, const float* __restrict__ n2b,
    const float* __restrict__ edge,
    const float* __restrict__ offw, const float* __restrict__ attww,
    const float* __restrict__ offb, const float* __restrict__ attwb,
    const float* __restrict__ l0w, const float* __restrict__ l0b)
{
    __shared__ float sm[5696];
    int bx = blockIdx.x;
    int t = threadIdx.x;

    if (bx >= 128) {
        if (bx < 368) {
            int idx = bx - 128;
            gemm_core(offw, attww, l0w, nullptr, g_Wc, 640, 256,
                      0, 3, 1, 640, (idx / 10) * 16, (idx % 10) * 64, sm, 0, 256);
        } else if (bx < 416) {
            float* Ts = sm;
            if (t < 32) Ts[t] = (float)pow(10000.0, (double)t / 32.0);
            __syncthreads();
            int g = bx - 368;
            geom_pe(edge, g * 8 + (t >> 5), t & 31, Ts[t & 31]);
        } else {
            int gw = (bx - 416) * 8 + (t >> 5), lane = t & 31;
            float4 b0 = *(const float4*)(l0b + lane * 4);
            float4 b1 = *(const float4*)(l0b + 128 + lane * 4);
            for (int i = 0; i < 24; i++) {
                int r = gw * 24 + i;
                const float* row = (r < 256) ? (offw + (size_t)r * 256)
                                             : (attww + (size_t)(r - 256) * 256);
                float4 w0 = *(const float4*)(row + lane * 4);
                float4 w1 = *(const float4*)(row + 128 + lane * 4);
                float p = dot4(w0, b0) + dot4(w1, b1);
                p = warp_sum(p);
                if (lane == 0)
                    g_biasc[r] = p + (r < 256 ? offb[r] : attwb[r - 256]);
            }
        }
        return;
    }

    // ---- attention for edge e = bx ----
    int e = bx;
    float* sq = sm;           // 256
    float* sc = sm + 256;     // 1024
    float* so = sm + 1280;    // 256
    float* sy = sm + 1536;    // 256
    int wp = t >> 5, lane = t & 31;

    sq[t] = g_qkout[e * 768 + t];
    __syncthreads();

    {
        int hq = lane >> 2, qd = lane & 3;
        float4 q0 = *(const float4*)(sq + hq * 32 + qd * 8);
        float4 q1 = *(const float4*)(sq + hq * 32 + qd * 8 + 4);
        const float scale = 0.17677669529663687f;
#pragma unroll 4
        for (int i = 0; i < 16; i++) {
            int f = wp + i * 8;
            const float4* kr = (const float4*)(g_qkout + (size_t)f * 768 + 256);
            float4 k0 = __ldg(kr + lane * 2);
            float4 k1 = __ldg(kr + lane * 2 + 1);
            float p = dot4(q0, k0) + dot4(q1, k1);
            p += __shfl_xor_sync(0xffffffffu, p, 1);
            p += __shfl_xor_sync(0xffffffffu, p, 2);
            if ((lane & 3) == 0) sc[hq * 128 + f] = p * scale;
        }
    }
    __syncthreads();
    {
        float vals[4];
        float m = -1e30f;
#pragma unroll
        for (int i = 0; i < 4; i++) { vals[i] = sc[wp * 128 + lane + 32 * i]; m = fmaxf(m, vals[i]); }
        m = warp_max(m);
        float sum = 0.f;
#pragma unroll
        for (int i = 0; i < 4; i++) { vals[i] = expf(vals[i] - m); sum += vals[i]; }
        sum = warp_sum(sum);
        float inv = 1.0f / sum;
#pragma unroll
        for (int i = 0; i < 4; i++) sc[wp * 128 + lane + 32 * i] = vals[i] * inv;
    }
    __syncthreads();
    {
        int h = t >> 5;
        float acc = 0.f;
#pragma unroll 4
        for (int f = 0; f < 128; f++)
            acc += sc[h * 128 + f] * __ldg(g_qkout + (size_t)f * 768 + 512 + t);
        so[t] = acc;
    }
    __syncthreads();
    {
        const float4* so4 = (const float4*)so;
        float4 s0 = so4[lane], s1 = so4[32 + lane];
#pragma unroll 4
        for (int i = 0; i < 32; i++) {
            int o = wp * 32 + i;
            const float4* r = (const float4*)(wo + (size_t)o * 256);
            float p = dot4(__ldg(r + lane), s0) + dot4(__ldg(r + 32 + lane), s1);
            p = warp_sum(p);
            if (lane == 0) sy[o] = p;
        }
    }
    __syncthreads();
    float y = tgt[e * 256 + t] + sy[t] + bo[t];
    g_x[e * 256 + t] = block_ln256(y, n2w, n2b, t);
}

// ================= offatt (split-K=2): partials into g_offatt / g_offatt2 ====
__global__ __launch_bounds__(256) void k_offatt(const float* __restrict__ qpos)
{
    __shared__ float sm[5696];
    int z = blockIdx.z;
    float* dst = z ? g_offatt2 : g_offatt;
    const float* bias = z ? nullptr : g_biasc;
    gemm_core(g_x, qpos, g_Wc, bias, dst, 384, 640,
              0, 2, 0, 0, blockIdx.y * 16, blockIdx.x * 64, sm,
              z * 320, 320);
}

// ================= sample: tap precompute + gather (raw agg out) =============
__global__ __launch_bounds__(512) void k_sample2(
    const float* __restrict__ src, const unsigned char* __restrict__ msk,
    const float* __restrict__ vr)
{
    int n = blockIdx.x, t = threadIdx.x;
    __shared__ float sloc[256];
    __shared__ float saw[128];
    __shared__ float mh[8], sh[8];
    __shared__ __align__(8) float2 std_[512];    // {pix (bitcast), coeff}
    if (t >= 256 && t < 384)
        saw[t - 256] = g_offatt[n * 384 + t] + g_offatt2[n * 384 + t];
    if (t < 256) {
        const float slen[4] = {32.f, 16.f, 8.f, 4.f};
        int l = (t >> 3) & 3, xy = t & 1;
        float off = g_offatt[n * 384 + t] + g_offatt2[n * 384 + t];
        sloc[t] = g_ref[n * 2 + xy] * vr[l * 2 + xy] + off / slen[l];
    }
    __syncthreads();
    if (t < 8) {
        float m = -1e30f;
        for (int i = 0; i < 16; i++) m = fmaxf(m, saw[t * 16 + i]);
        float s = 0.f;
        for (int i = 0; i < 16; i++) s += expf(saw[t * 16 + i] - m);
        mh[t] = m; sh[t] = s;
    }
    __syncthreads();
    if (t < 128) {
        int h = t >> 4;
        saw[t] = expf(saw[t] - mh[h]) / sh[h];
    }
    __syncthreads();

    {
        int h = t >> 6, l = (t >> 4) & 3, p = (t >> 2) & 3, tp = t & 3;
        const int s_arr[4]  = {32, 16, 8, 4};
        const int w_arr[4]  = {256, 128, 64, 32};
        const int st_arr[4] = {0, 65536, 81920, 86016};
        int s = s_arr[l], W = w_arr[l], base = st_arr[l];
        int lxl = g_lx[n * 4 + l], lyl = g_ly[n * 4 + l];
        float gx = sloc[h * 32 + l * 8 + p * 2 + 0];
        float gy = sloc[h * 32 + l * 8 + p * 2 + 1];
        float a  = saw[h * 16 + l * 4 + p];
        float px = gx * (float)s - 0.5f;
        float py = gy * (float)s - 0.5f;
        float fx0 = floorf(px), fy0 = floorf(py);
        int x0 = (int)fx0, y0 = (int)fy0;
        float fx = px - fx0, fy = py - fy0;
        int xi = x0 + (tp & 1), yi = y0 + (tp >> 1);
        float wx = (tp & 1) ? fx : (1.f - fx);
        float wy = (tp >> 1) ? fy : (1.f - fy);
        bool ok = (xi >= 0) & (xi < s) & (yi >= 0) & (yi < s);
        int xc = min(max(xi, 0), s - 1);
        int yc = min(max(yi, 0), s - 1);
        int pix = base + (lyl + yc) * W + (lxl + xc);
        ok = ok && !msk[pix];
        float c = ok ? a * (wx * wy) : 0.f;
        std_[t] = make_float2(__int_as_float(pix), c);
    }
    __syncthreads();

    int w = t >> 5;
    int h = w >> 1, half = w & 1, lane = t & 31;
    int doff = half * 32 + lane;
    ulonglong2 acc;
    acc.x = pack2(0.f, 0.f);
    acc.y = pack2(0.f, 0.f);
    float csum = 0.f;
    const float2* taps = std_ + h * 64;
#pragma unroll 8
    for (int i = 0; i < 64; i++) {
        float2 e2 = taps[i];
        int pix = __float_as_int(e2.x);
        float c = e2.y;
        csum += c;
        ull cp = pack2(c, c);
        ulonglong2 v = __ldg((const ulonglong2*)(src + (size_t)pix * 256) + doff);
        fma2(acc.x, cp, v.x);
        fma2(acc.y, cp, v.y);
    }
    ((ulonglong2*)(g_agg + (size_t)n * 2048 + h * 256))[doff] = acc;
    if (half == 0 && lane == 0) g_csum[n * 8 + h] = csum;
}

// ================= tail: pooled valproj + oproj + LN1 + FFN + LN3 ===========
// 64 blocks, 512 threads, 2 edges/block (R10-proven structure).
__global__ __launch_bounds__(512) void k_tail(
    const float* __restrict__ valw, const float* __restrict__ valb,
    const float* __restrict__ oprojw, const float* __restrict__ oprojb,
    const float* __restrict__ n1w, const float* __restrict__ n1b,
    const float* __restrict__ l1w, const float* __restrict__ l1b,
    const float* __restrict__ l2w, const float* __restrict__ l2b,
    const float* __restrict__ n3w, const float* __restrict__ n3b,
    float* __restrict__ out)
{
    __shared__ __align__(16) float sop[512];
    __shared__ float sy[512];
    __shared__ __align__(16) float sx2[512];
    __shared__ __align__(16) float shid[2048];
    __shared__ float sf[512];
    __shared__ float red[16];

    int t = threadIdx.x;
    int w = t >> 5, lane = t & 31;
    int ei = t >> 8, tt = t & 255, wp8 = tt >> 5;
    int e0 = blockIdx.x * 2;
    int e = e0 + ei;

    // ---- value projection on pooled agg (weights shared across both edges) --
    {
        int h = w >> 1;
        int jb = (w & 1) * 16;
        const float4* a0p = (const float4*)(g_agg + (size_t)(3 * e0 + 0) * 2048 + h * 256);
        const float4* a1p = (const float4*)(g_agg + (size_t)(3 * e0 + 1) * 2048 + h * 256);
        const float4* a2p = (const float4*)(g_agg + (size_t)(3 * e0 + 2) * 2048 + h * 256);
        const float4* b0p = (const float4*)(g_agg + (size_t)(3 * e0 + 3) * 2048 + h * 256);
        const float4* b1p = (const float4*)(g_agg + (size_t)(3 * e0 + 4) * 2048 + h * 256);
        const float4* b2p = (const float4*)(g_agg + (size_t)(3 * e0 + 5) * 2048 + h * 256);
        const float third = 1.f / 3.f;
        float4 u, v, z;
        u = a0p[lane]; v = a1p[lane]; z = a2p[lane];
        float4 av0 = make_float4((u.x + v.x + z.x) * third, (u.y + v.y + z.y) * third,
                                 (u.z + v.z + z.z) * third, (u.w + v.w + z.w) * third);
        u = a0p[32 + lane]; v = a1p[32 + lane]; z = a2p[32 + lane];
        float4 av1 = make_float4((u.x + v.x + z.x) * third, (u.y + v.y + z.y) * third,
                                 (u.z + v.z + z.z) * third, (u.w + v.w + z.w) * third);
        u = b0p[lane]; v = b1p[lane]; z = b2p[lane];
        float4 bv0 = make_float4((u.x + v.x + z.x) * third, (u.y + v.y + z.y) * third,
                                 (u.z + v.z + z.z) * third, (u.w + v.w + z.w) * third);
        u = b0p[32 + lane]; v = b1p[32 + lane]; z = b2p[32 + lane];
        float4 bv1 = make_float4((u.x + v.x + z.x) * third, (u.y + v.y + z.y) * third,
                                 (u.z + v.z + z.z) * third, (u.w + v.w + z.w) * third);
        float csa = (g_csum[(3 * e0 + 0) * 8 + h] + g_csum[(3 * e0 + 1) * 8 + h] +
                     g_csum[(3 * e0 + 2) * 8 + h]) * third;
        float csb = (g_csum[(3 * e0 + 3) * 8 + h] + g_csum[(3 * e0 + 4) * 8 + h] +
                     g_csum[(3 * e0 + 5) * 8 + h]) * third;
#pragma unroll 4
        for (int i = 0; i < 16; i++) {
            int o = h * 32 + jb + i;
            const float4* r = (const float4*)(valw + (size_t)o * 256);
            float4 w0 = __ldg(r + lane), w1 = __ldg(r + 32 + lane);
            float pa = dot4(w0, av0) + dot4(w1, av1);
            float pb = dot4(w0, bv0) + dot4(w1, bv1);
            pa = warp_sum(pa); pb = warp_sum(pb);
            float vb = __ldg(valb + o);
            if (lane == 0) sop[o] = pa + csa * vb;
            if (lane == 1) sop[256 + o] = pb + csb * vb;
        }
    }
    __syncthreads();

    // ---- oproj for both edges, weights loaded once ----
    {
        const float4* m0 = (const float4*)sop;
        const float4* m1 = (const float4*)(sop + 256);
        float4 a0 = m0[lane], a1 = m0[32 + lane];
        float4 b0 = m1[lane], b1 = m1[32 + lane];
#pragma unroll
        for (int i = 0; i < 16; i += 2) {
            int o = w * 16 + i;
            const float4* r0 = (const float4*)(oprojw + (size_t)o * 256);
            const float4* r1 = (const float4*)(oprojw + (size_t)(o + 1) * 256);
            float4 w00 = __ldg(r0 + lane), w01 = __ldg(r0 + 32 + lane);
            float4 w10 = __ldg(r1 + lane), w11 = __ldg(r1 + 32 + lane);
            float p00 = dot4(w00, a0) + dot4(w01, a1);
            float p01 = dot4(w10, a0) + dot4(w11, a1);
            float p10 = dot4(w00, b0) + dot4(w01, b1);
            float p11 = dot4(w10, b0) + dot4(w11, b1);
            p00 = warp_sum(p00); p01 = warp_sum(p01);
            p10 = warp_sum(p10); p11 = warp_sum(p11);
            if (lane == 0) sy[o] = p00;
            if (lane == 1) sy[o + 1] = p01;
            if (lane == 2) sy[256 + o] = p10;
            if (lane == 3) sy[256 + o + 1] = p11;
        }
    }
    __syncthreads();
    // ---- residual + norm1 ----
    {
        float y = g_x[(size_t)e * 256 + tt] + sy[ei * 256 + tt] + oprojb[tt];
        float x2 = ln_half(y, n1w[tt], n1b[tt], lane, wp8, red + ei * 8);
        sx2[ei * 256 + tt] = x2;
    }
    __syncthreads();

    // ---- FFN1 + relu (1024 hidden, both edges) ----
    {
        const float4* x0p = (const float4*)sx2;
        const float4* x1p = (const float4*)(sx2 + 256);
        float4 x00 = x0p[lane], x01 = x0p[32 + lane];
        float4 x10 = x1p[lane], x11 = x1p[32 + lane];
        for (int i = 0; i < 64; i += 2) {
            int o = w * 64 + i;
            const float4* r0 = (const float4*)(l1w + (size_t)o * 256);
            const float4* r1 = (const float4*)(l1w + (size_t)(o + 1) * 256);
            float4 w00 = __ldg(r0 + lane), w01 = __ldg(r0 + 32 + lane);
            float4 w10 = __ldg(r1 + lane), w11 = __ldg(r1 + 32 + lane);
            float p00 = dot4(w00, x00) + dot4(w01, x01);
            float p01 = dot4(w10, x00) + dot4(w11, x01);
            float p10 = dot4(w00, x10) + dot4(w01, x11);
            float p11 = dot4(w10, x10) + dot4(w11, x11);
            p00 = warp_sum(p00); p01 = warp_sum(p01);
            p10 = warp_sum(p10); p11 = warp_sum(p11);
            if (lane == 0) shid[o] = fmaxf(p00 + l1b[o], 0.f);
            if (lane == 1) shid[o + 1] = fmaxf(p01 + l1b[o + 1], 0.f);
            if (lane == 2) shid[1024 + o] = fmaxf(p10 + l1b[o], 0.f);
            if (lane == 3) shid[1024 + o + 1] = fmaxf(p11 + l1b[o + 1], 0.f);
        }
    }
    __syncthreads();
    // ---- FFN2 (K=1024, both edges) ----
    {
        const float4* h0p = (const float4*)shid;
        const float4* h1p = (const float4*)(shid + 1024);
#pragma unroll
        for (int i = 0; i < 16; i += 2) {
            int o = w * 16 + i;
            const float4* r0 = (const float4*)(l2w + (size_t)o * 1024);
            const float4* r1 = (const float4*)(l2w + (size_t)(o + 1) * 1024);
            float p00 = 0.f, p01 = 0.f, p10 = 0.f, p11 = 0.f;
#pragma unroll
            for (int j = 0; j < 8; j++) {
                float4 wv0 = __ldg(r0 + j * 32 + lane);
                float4 wv1 = __ldg(r1 + j * 32 + lane);
                float4 h0 = h0p[j * 32 + lane];
                float4 h1 = h1p[j * 32 + lane];
                p00 += dot4(wv0, h0); p01 += dot4(wv1, h0);
                p10 += dot4(wv0, h1); p11 += dot4(wv1, h1);
            }
            p00 = warp_sum(p00); p01 = warp_sum(p01);
            p10 = warp_sum(p10); p11 = warp_sum(p11);
            if (lane == 0) sf[o] = p00;
            if (lane == 1) sf[o + 1] = p01;
            if (lane == 2) sf[256 + o] = p10;
            if (lane == 3) sf[256 + o + 1] = p11;
        }
    }
    __syncthreads();
    // ---- residual + norm3 -> out ----
    {
        float y = sx2[ei * 256 + tt] + sf[ei * 256 + tt] + l2b[tt];
        out[(size_t)e * 256 + tt] = ln_half(y, n3w[tt], n3b[tt], lane, wp8, red + ei * 8);
    }
}

// ================= launch =================
extern "C" void kernel_launch(void* const* d_in, const int* in_sizes, int n_in,
                              void* d_out, int out_size) {
    const float* tgt      = (const float*)d_in[0];
    const float* qpos     = (const float*)d_in[1];
    const float* edge     = (const float*)d_in[2];
    const float* src      = (const float*)d_in[3];
    const unsigned char* msk = (const unsigned char*)d_in[4];
    const float* vr       = (const float*)d_in[5];
    const float* inw      = (const float*)d_in[6];
    const float* inb      = (const float*)d_in[7];
    const float* ow       = (const float*)d_in[8];
    const float* ob       = (const float*)d_in[9];
    const float* n1w      = (const float*)d_in[10];
    const float* n1b      = (const float*)d_in[11];
    const float* n2w      = (const float*)d_in[12];
    const float* n2b      = (const float*)d_in[13];
    const float* n3w      = (const float*)d_in[14];
    const float* n3b      = (const float*)d_in[15];
    const float* l0w      = (const float*)d_in[16];
    const float* l0b      = (const float*)d_in[17];
    const float* l1w      = (const float*)d_in[18];
    const float* l1b      = (const float*)d_in[19];
    const float* l2w      = (const float*)d_in[20];
    const float* l2b      = (const float*)d_in[21];
    const float* offw     = (const float*)d_in[22];
    const float* offb     = (const float*)d_in[23];
    const float* attww    = (const float*)d_in[24];
    const float* attwb    = (const float*)d_in[25];
    const float* valw     = (const float*)d_in[26];
    const float* valb     = (const float*)d_in[27];
    const float* oprojw   = (const float*)d_in[28];
    const float* oprojb   = (const float*)d_in[29];
    float* out = (float*)d_out;

    // 1. QKV projection
    k_qkv<<<dim3(12, 8), 256>>>(tgt, qpos, inw, inb);
    // 2. attn first (blocks 0-127) + overlapped Wc GEMM / geometry / bias
    k_phase2<<<418, 256>>>(ow, ob, tgt, n2w, n2b, edge,
                           offw, attww, offb, attwb, l0w, l0b);
    // 3. offsets + attention logits, split-K=2 (288 blocks, half serial chain)
    k_offatt<<<dim3(6, 24, 2), 256>>>(qpos);
    // 4. deformable sampling (sums split-K partials in prologue)
    k_sample2<<<384, 512>>>(src, msk, vr);
    // 5. pooled valproj + oproj + LN1 + FFN + LN3 (2 edges/block, 64 blocks)
    k_tail<<<64, 512>>>(valw, valb, oprojw, oprojb, n1w, n1b,
                        l1w, l1b, l2w, l2b, n3w, n3b, out);
}